// round 11
// baseline (speedup 1.0000x reference)
#include <cuda_runtime.h>
#include <cuda_fp16.h>
#include <math.h>

#define NB 16
#define NH 16
#define NHD 64
#define ND 1024
#define NL 513
#define NP 1024

#define NX4   2101248   // x        16*513*1024 /4
#define NQW4   786432   // qkv_w    3072*1024   /4
#define NPW4   262144   // pos_w    1024*1024   /4
#define NPE4  4194304   // pe       16*16*64*1024 /4
#define NOW4   262144   // out_w    1024*1024   /4

// Scratch (allocation-free rule: __device__ globals). fp16 everywhere.
__device__ __half g_Xh   [NX4*4];
__device__ __half g_QKVWh[NQW4*4];
__device__ __half g_POSWh[NPW4*4];
__device__ __half g_PEh  [NPE4*4];
__device__ __half g_OUTWh[NOW4*4];
__device__ __half g_QCh[NB*NH*NL*NHD];   // q + content_bias
__device__ __half g_QPh[NB*NH*NL*NHD];   // q + position_bias
__device__ __half g_Kh [NB*NH*NL*NHD];
__device__ __half g_Vh [NB*NH*NL*NHD];
__device__ __half g_PTh[NB*NH*NP*NHD];
__device__ __half g_CTXh[NB*NL*ND];      // attention output (fp16)

__device__ __forceinline__ void mma_f16(float* d, const uint4& a, const uint2& b) {
    asm volatile(
        "mma.sync.aligned.m16n8k16.row.col.f32.f16.f16.f32 "
        "{%0,%1,%2,%3}, {%4,%5,%6,%7}, {%8,%9}, {%0,%1,%2,%3};"
        : "+f"(d[0]), "+f"(d[1]), "+f"(d[2]), "+f"(d[3])
        : "r"(a.x), "r"(a.y), "r"(a.z), "r"(a.w), "r"(b.x), "r"(b.y));
}

__device__ __forceinline__ void ldsm_x4(uint4& d, const unsigned* p) {
    unsigned a = (unsigned)__cvta_generic_to_shared((void*)p);
    asm volatile("ldmatrix.sync.aligned.m8n8.x4.shared.b16 {%0,%1,%2,%3}, [%4];"
                 : "=r"(d.x), "=r"(d.y), "=r"(d.z), "=r"(d.w) : "r"(a));
}
__device__ __forceinline__ void ldsm_x2(uint2& d, const unsigned* p) {
    unsigned a = (unsigned)__cvta_generic_to_shared((void*)p);
    asm volatile("ldmatrix.sync.aligned.m8n8.x2.shared.b16 {%0,%1}, [%2];"
                 : "=r"(d.x), "=r"(d.y) : "r"(a));
}

__device__ __forceinline__ unsigned ldh2(const __half* p) {
    return *(const unsigned*)p;
}
__device__ __forceinline__ unsigned pkh2f(float x, float y) {
    __half2 h = __floats2half2_rn(x, y);
    return *(unsigned*)&h;
}
__device__ __forceinline__ unsigned pkhh(__half x, __half y) {
    __half2 h = __halves2half2(x, y);
    return *(unsigned*)&h;
}

// ---------------------------------------------------------------------------
// One-shot fp32 -> fp16 conversion of all GEMM inputs (bandwidth-bound).
// ---------------------------------------------------------------------------
__global__ void cvt_all(const float* __restrict__ x, const float* __restrict__ qw,
                        const float* __restrict__ pw, const float* __restrict__ pe,
                        const float* __restrict__ ow)
{
    int tid = blockIdx.x * blockDim.x + threadIdx.x;
    int stride = gridDim.x * blockDim.x;
#define CVT(SRC, DST, N4)                                    \
    for (int i = tid; i < (N4); i += stride) {               \
        float4 v = ((const float4*)(SRC))[i];                \
        uint2 o;                                             \
        o.x = pkh2f(v.x, v.y); o.y = pkh2f(v.z, v.w);        \
        ((uint2*)(DST))[i] = o;                              \
    }
    CVT(x,  g_Xh,    NX4)
    CVT(qw, g_QKVWh, NQW4)
    CVT(pw, g_POSWh, NPW4)
    CVT(pe, g_PEh,   NPE4)
    CVT(ow, g_OUTWh, NOW4)
#undef CVT
}

// ---------------------------------------------------------------------------
// f16 tensor-core GEMM (m16n8k16) with ldmatrix fragment loads.
// Row-major fp16 tiles in smem (rows padded to 80B -> conflict-free LDSM),
// double-buffered BK=32, one barrier/chunk. 256 thr / 8 warps, 2Mx4N of
// 64x32 warp tiles. Dynamic smem 40,960 B.
// ---------------------------------------------------------------------------
template<int EPI>
__global__ void __launch_bounds__(256, 2)
gemm_h(const __half* __restrict__ A, const __half* __restrict__ Bw,
       int M, int N,
       const float* __restrict__ bias,
       const float* __restrict__ cbias, const float* __restrict__ pbias,
       float* __restrict__ out)
{
    const int K = 1024;
    extern __shared__ unsigned gsm[];
    unsigned* sA = gsm;            // 2 x 2560 uints (128 rows x 20)
    unsigned* sB = gsm + 2 * 2560; // 2 x 2560

    int t = threadIdx.x, lane = t & 31, w = t >> 5;
    int warpM = w & 1, warpN = w >> 1;
    int m0 = blockIdx.y * 128, n0 = blockIdx.x * 128;

    // staging: thread covers row rs, halves [hs, hs+16)
    int rs = t >> 1;
    int hs = (t & 1) * 16;
    unsigned sbase = rs * 20 + (hs >> 1);

    // ldmatrix per-thread row offsets (uints)
    unsigned aOff = (warpM * 64 + ((lane >> 3) & 1) * 8 + (lane & 7)) * 20 + (lane >> 4) * 4;
    unsigned bOff = (warpN * 32 + (lane & 7)) * 20 + ((lane >> 3) & 1) * 4;

    float acc[4][4][4];
#pragma unroll
    for (int i = 0; i < 4; i++)
#pragma unroll
        for (int j = 0; j < 4; j++)
#pragma unroll
            for (int r = 0; r < 4; r++) acc[i][j][r] = 0.f;

    uint4 ra[2], rb[2];
    const uint4 z4 = make_uint4(0u, 0u, 0u, 0u);

#define GLOAD(KT) {                                                          \
        int gm = m0 + rs;                                                    \
        ra[0] = (gm < M) ? *(const uint4*)(A + (size_t)gm * K + (KT) + hs)     : z4; \
        ra[1] = (gm < M) ? *(const uint4*)(A + (size_t)gm * K + (KT) + hs + 8) : z4; \
        rb[0] = *(const uint4*)(Bw + (size_t)(n0 + rs) * K + (KT) + hs);     \
        rb[1] = *(const uint4*)(Bw + (size_t)(n0 + rs) * K + (KT) + hs + 8); \
    }

#define SSTORE(BI) {                                                         \
        unsigned ba = (BI) * 2560 + sbase;                                   \
        *(uint4*)&sA[ba] = ra[0]; *(uint4*)&sA[ba + 4] = ra[1];              \
        *(uint4*)&sB[ba] = rb[0]; *(uint4*)&sB[ba + 4] = rb[1];              \
    }

    GLOAD(0);
    SSTORE(0);
    __syncthreads();

    for (int c = 0; c < 32; c++) {
        int cur = c & 1;
        if (c < 31) GLOAD((c + 1) * 32);
#pragma unroll
        for (int s = 0; s < 2; s++) {
            uint4 av[4];
            uint2 bv[4];
#pragma unroll
            for (int i = 0; i < 4; i++)
                ldsm_x4(av[i], &sA[cur * 2560 + aOff + i * 320 + s * 8]);
#pragma unroll
            for (int j = 0; j < 4; j++)
                ldsm_x2(bv[j], &sB[cur * 2560 + bOff + j * 160 + s * 8]);
#pragma unroll
            for (int i = 0; i < 4; i++)
#pragma unroll
                for (int j = 0; j < 4; j++)
                    mma_f16(acc[i][j], av[i], bv[j]);
        }
        if (c < 31) SSTORE(1 - cur);
        __syncthreads();
    }
#undef GLOAD
#undef SSTORE

    int mb = m0 + warpM * 64 + (lane >> 2);
    int nb = n0 + warpN * 32 + (lane & 3) * 2;
#pragma unroll
    for (int i = 0; i < 4; i++) {
#pragma unroll
        for (int rr = 0; rr < 2; rr++) {
            int m = mb + i * 16 + rr * 8;
            if (m >= M) continue;
            if (EPI == 0) {
                int b_ = m / NL, l = m - b_ * NL;
#pragma unroll
                for (int j = 0; j < 4; j++) {
                    int n = nb + j * 8;            // even; pair (n, n+1) same part/head
                    float v0 = acc[i][j][rr * 2 + 0] + bias[n];
                    float v1 = acc[i][j][rr * 2 + 1] + bias[n + 1];
                    int part = n >> 10, c1 = n & 1023;
                    int hh = c1 >> 6, hd = c1 & 63;
                    size_t o = ((((size_t)b_ * NH + hh) * NL + l) << 6) + hd;
                    if (part == 0) {
                        *(unsigned*)&g_QCh[o] = pkh2f(v0 + cbias[c1], v1 + cbias[c1 + 1]);
                        *(unsigned*)&g_QPh[o] = pkh2f(v0 + pbias[c1], v1 + pbias[c1 + 1]);
                    } else if (part == 1) {
                        *(unsigned*)&g_Kh[o] = pkh2f(v0, v1);
                    } else {
                        *(unsigned*)&g_Vh[o] = pkh2f(v0, v1);
                    }
                }
            } else if (EPI == 1) {
                float bm = bias[m];
#pragma unroll
                for (int j = 0; j < 4; j++) {
                    int n = nb + j * 8;
                    float v0 = acc[i][j][rr * 2 + 0] + bm;
                    float v1 = acc[i][j][rr * 2 + 1] + bm;
                    int bh = n >> 6, hd = n & 63;
                    *(unsigned*)&g_PTh[((((size_t)bh) << 10) + m) * 64 + hd] = pkh2f(v0, v1);
                }
            } else {
#pragma unroll
                for (int j = 0; j < 4; j++) {
                    int n = nb + j * 8;
                    float2 st;
                    st.x = acc[i][j][rr * 2 + 0] + bias[n];
                    st.y = acc[i][j][rr * 2 + 1] + bias[n + 1];
                    *(float2*)(out + (size_t)m * ND + n) = st;
                }
            }
        }
    }
}

// ---------------------------------------------------------------------------
// Tensor-core fused attention, all-f16 MMA inputs; ctx stored fp16.
// CTA = (i-tile of 64 q, one b,h), 256 thr / 8 warps. smem 99,968B -> 2/SM.
// ---------------------------------------------------------------------------
__global__ void __launch_bounds__(256, 2)
attn_mma(const unsigned char* __restrict__ mask, __half* __restrict__ ctx)
{
    extern __shared__ char smraw[];
    __half*   sS  = (__half*)smraw;                   // [64][520] + 64 pad (66,688B)
    unsigned* sKG = (unsigned*)(smraw + 66688);       // K/V f16 frags | G (16,640B)
    unsigned* sP  = (unsigned*)(smraw + 83328);       // P band f16 frags (16,384B)
    float*    sSum= (float*)(smraw + 99712);          // [64]
    __half*   sG  = (__half*)sKG;                     // G view: [64][130] halves

    int t = threadIdx.x, lam = t & 31, w = t >> 5;
    int rg = w & 3, ch = w >> 2;
    int it = blockIdx.x, h = blockIdx.y, b = blockIdx.z;
    int i0 = it * 64;
    size_t bh = (size_t)b * NH + h;
    const __half* QCg = g_QCh + bh * NL * NHD;
    const __half* QPg = g_QPh + bh * NL * NHD;
    const __half* Kg  = g_Kh  + bh * NL * NHD;
    const __half* Vg  = g_Vh  + bh * NL * NHD;
    const __half* Pg  = g_PTh + bh * NP * NHD;

    // zero sS (incl. pads)
    for (int idx = t; idx < 16672; idx += 256) ((unsigned*)sS)[idx] = 0u;

    int gr0 = rg * 16 + (lam >> 2);
    int r0g = i0 + gr0, r1g = r0g + 8;
    int gt0 = 6 - 2 * rg;      // first G n8-tile needed by this row group

    int vkey = t >> 4;         // staging key base
    int vhd4 = (t & 15) * 4;   // staging hd base
    int la2  = (lam & 3) * 2;

    // QC / QP A-frags (f16, m16n8k16): 4 ksteps, register-resident
    uint4 qcf[4], qpf[4];
#pragma unroll
    for (int s = 0; s < 4; s++) {
        int c0 = s * 16 + la2;
        unsigned c00 = (r0g < NL) ? ldh2(QCg + r0g * 64 + c0)     : 0u;
        unsigned c10 = (r1g < NL) ? ldh2(QCg + r1g * 64 + c0)     : 0u;
        unsigned c01 = (r0g < NL) ? ldh2(QCg + r0g * 64 + c0 + 8) : 0u;
        unsigned c11 = (r1g < NL) ? ldh2(QCg + r1g * 64 + c0 + 8) : 0u;
        qcf[s] = make_uint4(c00, c10, c01, c11);
        unsigned p00 = (r0g < NL) ? ldh2(QPg + r0g * 64 + c0)     : 0u;
        unsigned p10 = (r1g < NL) ? ldh2(QPg + r1g * 64 + c0)     : 0u;
        unsigned p01 = (r0g < NL) ? ldh2(QPg + r0g * 64 + c0 + 8) : 0u;
        unsigned p11 = (r1g < NL) ? ldh2(QPg + r1g * 64 + c0 + 8) : 0u;
        qpf[s] = make_uint4(p00, p10, p01, p11);
    }

    // ===================== score phase =====================
    for (int jt = 0; jt < 9; jt++) {
        int j0 = jt * 64;
        __syncthreads();
        // stage K_j as f16 B-frags (k = hd, n = key)
        {
            int step = vhd4 >> 4, k16 = vhd4 & 15;
            unsigned boff = step * 520 + ((k16 & 7) >> 1) * 2 + (k16 >> 3);
#pragma unroll
            for (int u = 0; u < 4; u++) {
                int key = vkey + u * 16;
                int gk = j0 + key;
                uint2 kv = make_uint2(0u, 0u);
                if (gk < NL) kv = *(const uint2*)(Kg + (size_t)gk * 64 + vhd4);
                unsigned base = boff + (key >> 3) * 64 + (key & 7) * 8;
                sKG[base]     = kv.x;
                sKG[base + 2] = kv.y;
            }
        }
        // stage P band (128 rows x 64 hd) as f16 B-frags (k = hd, n = c)
        int pbase = j0 - i0 + 449;
#pragma unroll
        for (int u = 0; u < 8; u++) {
            int idx = u * 256 + t;
            int c = idx >> 4, d4 = (idx & 15) * 4;
            int p = pbase + c;
            uint2 pv = make_uint2(0u, 0u);
            if ((unsigned)p < (unsigned)NP)
                pv = *(const uint2*)(Pg + (size_t)p * 64 + d4);
            int step = d4 >> 4, k16 = d4 & 15;
            unsigned a0 = step * 1024 + (c >> 3) * 64 + ((c & 7) * 4 + ((k16 & 7) >> 1)) * 2 + (k16 >> 3);
            sP[a0]     = pv.x;
            sP[a0 + 2] = pv.y;
        }
        __syncthreads();

        // content MMA (f16): 4 ksteps x 4 n8-tiles
        float C[4][4];
#pragma unroll
        for (int nt = 0; nt < 4; nt++)
#pragma unroll
            for (int r = 0; r < 4; r++) C[nt][r] = 0.f;
#pragma unroll
        for (int s = 0; s < 4; s++) {
#pragma unroll
            for (int nt = 0; nt < 4; nt++) {
                uint2 bv = *(const uint2*)&sKG[s * 520 + (ch * 4 + nt) * 64 + lam * 2];
                mma_f16(C[nt], qcf[s], bv);
            }
        }
        // G MMA (f16): band-pruned, 5 tiles per col-half
        float G[5][4];
#pragma unroll
        for (int nt = 0; nt < 5; nt++)
#pragma unroll
            for (int r = 0; r < 4; r++) G[nt][r] = 0.f;
#pragma unroll
        for (int s = 0; s < 4; s++) {
#pragma unroll
            for (int nt = 0; nt < 5; nt++) {
                int tg = gt0 + ch * 5 + nt;
                uint2 bv = *(const uint2*)&sP[s * 1024 + tg * 64 + lam * 2];
                mma_f16(G[nt], qpf[s], bv);
            }
        }
        __syncthreads();   // content reads of sKG done before G overwrite
#pragma unroll
        for (int nt = 0; nt < 5; nt++) {
            int c0 = (gt0 + ch * 5 + nt) * 8 + la2;
            *(__half2*)&sG[gr0 * 130 + c0]       = __floats2half2_rn(G[nt][0], G[nt][1]);
            *(__half2*)&sG[(gr0 + 8) * 130 + c0] = __floats2half2_rn(G[nt][2], G[nt][3]);
        }
        __syncthreads();   // G visible
#pragma unroll
        for (int nt = 0; nt < 4; nt++) {
            int jjb = ch * 32 + nt * 8 + la2;
            float s0 = C[nt][0] + __half2float(sG[gr0 * 130 + (jjb - gr0 + 63)]);
            float s1 = C[nt][1] + __half2float(sG[gr0 * 130 + (jjb + 1 - gr0 + 63)]);
            float s2 = C[nt][2] + __half2float(sG[(gr0 + 8) * 130 + (jjb - gr0 - 8 + 63)]);
            float s3 = C[nt][3] + __half2float(sG[(gr0 + 8) * 130 + (jjb + 1 - gr0 - 8 + 63)]);
            if (j0 + jjb < NL) {
                *(__half2*)&sS[gr0 * 520 + j0 + jjb]       = __floats2half2_rn(s0, s1);
                *(__half2*)&sS[(gr0 + 8) * 520 + j0 + jjb] = __floats2half2_rn(s2, s3);
            }
        }
    }
    __syncthreads();

    // prefetch V tile for jt=0 — latency hides under softmax.
    uint2 va[2], vb[2];
#define VGLOAD(J0) {                                                         \
        _Pragma("unroll")                                                    \
        for (int u = 0; u < 2; u++) {                                        \
            int k0 = (J0) + 2 * vkey + 32 * u;                               \
            va[u] = (k0 < NL)     ? *(const uint2*)(Vg + (size_t)k0 * 64 + vhd4)       : make_uint2(0u, 0u); \
            vb[u] = (k0 + 1 < NL) ? *(const uint2*)(Vg + (size_t)(k0 + 1) * 64 + vhd4) : make_uint2(0u, 0u); \
        } }
    VGLOAD(0);

    // ===================== softmax (warp per row, half2) =====================
    for (int li = w * 8; li < w * 8 + 8; li++) {
        int i = i0 + li;
        if (i >= NL) { if (lam == 0) sSum[li] = 1.f; continue; }
        const unsigned char* mrow = mask + ((size_t)b * NL + i) * NL;
        __half2* srow2 = (__half2*)&sS[li * 520];
        float mx = -3.4028235e38f;
        for (int j2 = lam; j2 < 256; j2 += 32) {
            float2 v = __half22float2(srow2[j2]);
            v.x = mrow[2 * j2]     ? -3.4028235e38f : v.x * 0.125f;
            v.y = mrow[2 * j2 + 1] ? -3.4028235e38f : v.y * 0.125f;
            mx = fmaxf(mx, fmaxf(v.x, v.y));
        }
        if (lam == 0) {
            float v = __half2float(sS[li * 520 + 512]) * 0.125f;
            if (mrow[512]) v = -3.4028235e38f;
            mx = fmaxf(mx, v);
        }
#pragma unroll
        for (int o = 16; o > 0; o >>= 1) mx = fmaxf(mx, __shfl_xor_sync(0xffffffffu, mx, o));
        float s = 0.f;
        for (int j2 = lam; j2 < 256; j2 += 32) {
            float2 v = __half22float2(srow2[j2]);
            v.x = mrow[2 * j2]     ? -3.4028235e38f : v.x * 0.125f;
            v.y = mrow[2 * j2 + 1] ? -3.4028235e38f : v.y * 0.125f;
            float e0 = __expf(v.x - mx), e1 = __expf(v.y - mx);
            srow2[j2] = __floats2half2_rn(e0, e1);
            s += e0 + e1;
        }
        if (lam == 0) {
            float v = __half2float(sS[li * 520 + 512]) * 0.125f;
            if (mrow[512]) v = -3.4028235e38f;
            float e = __expf(v - mx);
            sS[li * 520 + 512] = __float2half_rn(e);
            s += e;
        }
#pragma unroll
        for (int o = 16; o > 0; o >>= 1) s += __shfl_xor_sync(0xffffffffu, s, o);
        if (lam == 0) sSum[li] = s;
    }
    __syncthreads();

    // ===================== AV phase (f16, V prefetched) =====================
    float O[4][4];
#pragma unroll
    for (int nt = 0; nt < 4; nt++)
#pragma unroll
        for (int r = 0; r < 4; r++) O[nt][r] = 0.f;

    for (int jt = 0; jt < 9; jt++) {
        int j0 = jt * 64;
        // store prefetched V as f16 B-frags: k = key, n = hd
#pragma unroll
        for (int u = 0; u < 2; u++) {
            int key0 = 2 * vkey + 32 * u;        // even local key
            __half2 a01 = *(__half2*)&va[u].x;
            __half2 a23 = *(__half2*)&va[u].y;
            __half2 b01 = *(__half2*)&vb[u].x;
            __half2 b23 = *(__half2*)&vb[u].y;
            unsigned o0 = pkhh(a01.x, b01.x);
            unsigned o1 = pkhh(a01.y, b01.y);
            unsigned o2 = pkhh(a23.x, b23.x);
            unsigned o3 = pkhh(a23.y, b23.y);
            int step = key0 >> 4, kk = key0 & 15;
            unsigned koff = step * 520 + ((kk & 7) >> 1) * 2 + (kk >> 3);
#pragma unroll
            for (int e = 0; e < 4; e++) {
                int n = vhd4 + e;
                unsigned addr = koff + (n >> 3) * 64 + (n & 7) * 8;
                sKG[addr] = (e == 0) ? o0 : (e == 1) ? o1 : (e == 2) ? o2 : o3;
            }
        }
        __syncthreads();
        if (jt < 8) VGLOAD(j0 + 64);
#pragma unroll
        for (int ks = 0; ks < 4; ks++) {
            int kc0 = j0 + ks * 16 + la2;
            unsigned a0 = *(const unsigned*)&sS[gr0 * 520 + kc0];
            unsigned a1 = *(const unsigned*)&sS[(gr0 + 8) * 520 + kc0];
            unsigned a2 = *(const unsigned*)&sS[gr0 * 520 + kc0 + 8];
            unsigned a3 = *(const unsigned*)&sS[(gr0 + 8) * 520 + kc0 + 8];
            uint4 av = make_uint4(a0, a1, a2, a3);
#pragma unroll
            for (int nt = 0; nt < 4; nt++) {
                uint2 bv = *(const uint2*)&sKG[ks * 520 + (ch * 4 + nt) * 64 + lam * 2];
                mma_f16(O[nt], av, bv);
            }
        }
        __syncthreads();   // MMA reads of sKG done before next V store
    }
#undef VGLOAD

    float l0 = 1.f / sSum[gr0];
    float l1 = 1.f / sSum[gr0 + 8];
#pragma unroll
    for (int nt = 0; nt < 4; nt++) {
        int hd = ch * 32 + nt * 8 + la2;
        if (r0g < NL) {
            *(unsigned*)&ctx[((size_t)b * NL + r0g) * ND + h * 64 + hd] =
                pkh2f(O[nt][0] * l0, O[nt][1] * l0);
        }
        if (r1g < NL) {
            *(unsigned*)&ctx[((size_t)b * NL + r1g) * ND + h * 64 + hd] =
                pkh2f(O[nt][2] * l1, O[nt][3] * l1);
        }
    }
}

// ---------------------------------------------------------------------------
extern "C" void kernel_launch(void* const* d_in, const int* in_sizes, int n_in,
                              void* d_out, int out_size)
{
    const float* x     = (const float*)d_in[0];
    const float* pe    = (const float*)d_in[1];
    const unsigned char* mask = (const unsigned char*)d_in[2];
    const float* qkv_w = (const float*)d_in[3];
    const float* qkv_b = (const float*)d_in[4];
    const float* pos_w = (const float*)d_in[5];
    const float* pos_b = (const float*)d_in[6];
    const float* out_w = (const float*)d_in[7];
    const float* out_b = (const float*)d_in[8];
    const float* cbias = (const float*)d_in[9];
    const float* pbias = (const float*)d_in[10];
    float* out = (float*)d_out;

    __half *xh, *qwh, *pwh, *peh, *owh, *ctxh;
    cudaGetSymbolAddress((void**)&xh,  g_Xh);
    cudaGetSymbolAddress((void**)&qwh, g_QKVWh);
    cudaGetSymbolAddress((void**)&pwh, g_POSWh);
    cudaGetSymbolAddress((void**)&peh, g_PEh);
    cudaGetSymbolAddress((void**)&owh, g_OUTWh);
    cudaGetSymbolAddress((void**)&ctxh, g_CTXh);

    const int M1 = NB * NL;                        // 8208
    const int GEMM_SMEM = 4 * 2560 * 4;            // 40,960 B
    const int ATTN_SMEM = 99968;
    cudaFuncSetAttribute(gemm_h<0>, cudaFuncAttributeMaxDynamicSharedMemorySize, GEMM_SMEM);
    cudaFuncSetAttribute(gemm_h<1>, cudaFuncAttributeMaxDynamicSharedMemorySize, GEMM_SMEM);
    cudaFuncSetAttribute(gemm_h<2>, cudaFuncAttributeMaxDynamicSharedMemorySize, GEMM_SMEM);
    cudaFuncSetAttribute(attn_mma, cudaFuncAttributeMaxDynamicSharedMemorySize, ATTN_SMEM);

    dim3 blk(256);
    cvt_all<<<1184, 256>>>(x, qkv_w, pos_w, pe, out_w);
    gemm_h<0><<<dim3(3072 / 128, (M1 + 127) / 128), blk, GEMM_SMEM>>>(
        xh, qwh, M1, 3072, qkv_b, cbias, pbias, nullptr);
    gemm_h<1><<<dim3(16384 / 128, 1024 / 128), blk, GEMM_SMEM>>>(
        pwh, peh, 1024, 16384, pos_b, nullptr, nullptr, nullptr);
    attn_mma<<<dim3(9, NH, NB), blk, ATTN_SMEM>>>(mask, ctxh);
    gemm_h<2><<<dim3(1024 / 128, (M1 + 127) / 128), blk, GEMM_SMEM>>>(
        ctxh, owh, M1, 1024, out_b, nullptr, nullptr, out);
}

// round 12
// speedup vs baseline: 1.0810x; 1.0810x over previous
#include <cuda_runtime.h>
#include <cuda_fp16.h>
#include <math.h>

#define NB 16
#define NH 16
#define NHD 64
#define ND 1024
#define NL 513
#define NP 1024

// Scratch (allocation-free rule: __device__ globals). fp16 intermediates.
__device__ __half g_QCh[NB*NH*NL*NHD];   // q + content_bias
__device__ __half g_QPh[NB*NH*NL*NHD];   // q + position_bias
__device__ __half g_Kh [NB*NH*NL*NHD];
__device__ __half g_Vh [NB*NH*NL*NHD];
__device__ __half g_PTh[NB*NH*NP*NHD];
__device__ float  g_CTX[NB*NL*ND];       // attention output (fp32)

__device__ __forceinline__ void mma_f16(float* d, const uint4& a, const uint2& b) {
    asm volatile(
        "mma.sync.aligned.m16n8k16.row.col.f32.f16.f16.f32 "
        "{%0,%1,%2,%3}, {%4,%5,%6,%7}, {%8,%9}, {%0,%1,%2,%3};"
        : "+f"(d[0]), "+f"(d[1]), "+f"(d[2]), "+f"(d[3])
        : "r"(a.x), "r"(a.y), "r"(a.z), "r"(a.w), "r"(b.x), "r"(b.y));
}

__device__ __forceinline__ unsigned pkh2f(float x, float y) {
    __half2 h = __floats2half2_rn(x, y);
    return *(unsigned*)&h;
}
__device__ __forceinline__ unsigned pkhh(__half x, __half y) {
    __half2 h = __halves2half2(x, y);
    return *(unsigned*)&h;
}

// ---------------------------------------------------------------------------
// f16 tensor-core GEMM (m16n8k16), double-buffered BK=32, ONE barrier/chunk
// (R10 measured-best config). fp32 sources cvt'd to half2 during staging.
// 256 thr / 8 warps (2M x 4N of 64x32 tiles). Dynamic smem 33,376 B.
// ---------------------------------------------------------------------------
template<int EPI>
__global__ void __launch_bounds__(256, 2)
gemm_f16(const float* __restrict__ A, const float* __restrict__ Bw,
         int M, int N,
         const float* __restrict__ bias,
         const float* __restrict__ cbias, const float* __restrict__ pbias,
         float* __restrict__ out)
{
    const int K = 1024;
    extern __shared__ unsigned gsm[];
    unsigned* sA = gsm;            // 2 x 2120
    unsigned* sB = gsm + 2 * 2120; // 2 x 2052

    int t    = threadIdx.x;
    int lane = t & 31, w = t >> 5;
    int warpM = w & 1, warpN = w >> 1;
    int m0 = blockIdx.y * 128, n0 = blockIdx.x * 128;

    int lrow = t >> 3;
    int lkq  = t & 7;
    int kk0  = lkq * 4;
    int sstep = kk0 >> 4;
    int c16  = kk0 & 15;

    unsigned baA[4], baB[4];
#pragma unroll
    for (int u = 0; u < 4; u++) {
        int ml = lrow + u * 32;
        int mt = ml >> 4, mr = ml & 15;
        baA[u] = sstep * 1060 + mt * 132
               + ((mr & 7) * 4 + ((c16 & 7) >> 1)) * 4
               + (c16 >> 3) * 2 + (mr >> 3);
        baB[u] = sstep * 1026 + (ml >> 3) * 64
               + ((ml & 7) * 4 + ((c16 & 7) >> 1)) * 2
               + (c16 >> 3);
    }

    float acc[4][4][4];
#pragma unroll
    for (int i = 0; i < 4; i++)
#pragma unroll
        for (int j = 0; j < 4; j++)
#pragma unroll
            for (int r = 0; r < 4; r++) acc[i][j][r] = 0.f;

    float4 ra[4], rb[4];
    const float4 z4 = make_float4(0.f, 0.f, 0.f, 0.f);

#define GLOAD(KT) {                                                          \
        _Pragma("unroll")                                                    \
        for (int u = 0; u < 4; u++) {                                        \
            int gm = m0 + lrow + u * 32;                                     \
            ra[u] = (gm < M) ? *(const float4*)(A + (size_t)gm * K + (KT) + kk0) : z4; \
            rb[u] = *(const float4*)(Bw + (size_t)(n0 + lrow + u * 32) * K + (KT) + kk0); \
        } }

#define SSTORE(BI) {                                                         \
        _Pragma("unroll")                                                    \
        for (int u = 0; u < 4; u++) {                                        \
            unsigned ba = (BI) * 2120 + baA[u];                              \
            sA[ba + 0] = pkh2f(ra[u].x, ra[u].y);                            \
            sA[ba + 4] = pkh2f(ra[u].z, ra[u].w);                            \
            unsigned bb = (BI) * 2052 + baB[u];                              \
            sB[bb + 0] = pkh2f(rb[u].x, rb[u].y);                            \
            sB[bb + 2] = pkh2f(rb[u].z, rb[u].w);                            \
        } }

    GLOAD(0);
    SSTORE(0);
    __syncthreads();

    for (int c = 0; c < 32; c++) {
        int cur = c & 1;
        if (c < 31) GLOAD((c + 1) * 32);
#pragma unroll
        for (int s = 0; s < 2; s++) {
            uint4 av[4];
            uint2 bv[4];
#pragma unroll
            for (int i = 0; i < 4; i++)
                av[i] = *(const uint4*)&sA[cur * 2120 + s * 1060 + (warpM * 4 + i) * 132 + lane * 4];
#pragma unroll
            for (int j = 0; j < 4; j++)
                bv[j] = *(const uint2*)&sB[cur * 2052 + s * 1026 + (warpN * 4 + j) * 64 + lane * 2];
#pragma unroll
            for (int i = 0; i < 4; i++)
#pragma unroll
                for (int j = 0; j < 4; j++)
                    mma_f16(acc[i][j], av[i], bv[j]);
        }
        if (c < 31) SSTORE(1 - cur);
        __syncthreads();
    }
#undef GLOAD
#undef SSTORE

    int mb = m0 + warpM * 64 + (lane >> 2);
    int nb = n0 + warpN * 32 + (lane & 3) * 2;
#pragma unroll
    for (int i = 0; i < 4; i++) {
#pragma unroll
        for (int rr = 0; rr < 2; rr++) {
            int m = mb + i * 16 + rr * 8;
            if (m >= M) continue;
            if (EPI == 0) {
                int b_ = m / NL, l = m - b_ * NL;
#pragma unroll
                for (int j = 0; j < 4; j++) {
                    int n = nb + j * 8;
                    float v0 = acc[i][j][rr * 2 + 0] + bias[n];
                    float v1 = acc[i][j][rr * 2 + 1] + bias[n + 1];
                    int part = n >> 10, c1 = n & 1023;
                    int hh = c1 >> 6, hd = c1 & 63;
                    size_t o = ((((size_t)b_ * NH + hh) * NL + l) << 6) + hd;
                    if (part == 0) {
                        *(unsigned*)&g_QCh[o] = pkh2f(v0 + cbias[c1], v1 + cbias[c1 + 1]);
                        *(unsigned*)&g_QPh[o] = pkh2f(v0 + pbias[c1], v1 + pbias[c1 + 1]);
                    } else if (part == 1) {
                        *(unsigned*)&g_Kh[o] = pkh2f(v0, v1);
                    } else {
                        *(unsigned*)&g_Vh[o] = pkh2f(v0, v1);
                    }
                }
            } else if (EPI == 1) {
                float bm = bias[m];
#pragma unroll
                for (int j = 0; j < 4; j++) {
                    int n = nb + j * 8;
                    float v0 = acc[i][j][rr * 2 + 0] + bm;
                    float v1 = acc[i][j][rr * 2 + 1] + bm;
                    int bh = n >> 6, hd = n & 63;
                    *(unsigned*)&g_PTh[((((size_t)bh) << 10) + m) * 64 + hd] = pkh2f(v0, v1);
                }
            } else {
#pragma unroll
                for (int j = 0; j < 4; j++) {
                    int n = nb + j * 8;
                    float2 st;
                    st.x = acc[i][j][rr * 2 + 0] + bias[n];
                    st.y = acc[i][j][rr * 2 + 1] + bias[n + 1];
                    *(float2*)(out + (size_t)m * ND + n) = st;
                }
            }
        }
    }
}

// ---------------------------------------------------------------------------
// Flash-style fused attention: register-resident S, online softmax.
// CTA = (i-tile of 64 q, one b,h), 256 thr / 8 warps: rg=w&3 (16 rows),
// ch=w>>2 (32-col chunk). Per jt: stage K/V/P(circular), content+G MMA,
// G smem gather, mask+online-softmax in regs, exp(S) -> A-frags -> AV MMA.
// End: split-k merge of the two ch warps via smem. 2 barriers per jt.
// Dynamic smem 49,664 B -> 2 CTAs/SM.
// ---------------------------------------------------------------------------
__global__ void __launch_bounds__(256, 2)
attn_flash(const unsigned char* __restrict__ mask, float* __restrict__ ctx)
{
    extern __shared__ unsigned smu[];
    unsigned* sK = smu;                 // 2080 uints (4 x 520)
    unsigned* sV = smu + 2080;          // 2080 uints
    unsigned* sP = smu + 4160;          // 4096 uints (4 x 1024)
    __half*   sG = (__half*)(smu + 8256); // 64 x 130 halves (4160 uints)
    // end-of-kernel merge overlay (after barrier):
    float* mO  = (float*)smu;           // [64][68]
    float* mml = (float*)smu + 64 * 68; // [64][2]

    const float NEG = -3.4028235e38f;
    int t = threadIdx.x, lam = t & 31, w = t >> 5;
    int rg = w & 3, ch = w >> 2;
    int it = blockIdx.x, h = blockIdx.y, b = blockIdx.z;
    int i0 = it * 64;
    size_t bh = (size_t)b * NH + h;
    const __half* QCg = g_QCh + bh * NL * NHD;
    const __half* QPg = g_QPh + bh * NL * NHD;
    const __half* Kg  = g_Kh  + bh * NL * NHD;
    const __half* Vg  = g_Vh  + bh * NL * NHD;
    const __half* Pg  = g_PTh + bh * NP * NHD;

    int gr0 = rg * 16 + (lam >> 2);
    int r0g = i0 + gr0, r1g = r0g + 8;
    int gt0 = 6 - 2 * rg;
    int vkey = t >> 4;
    int vhd4 = (t & 15) * 4;
    int la2  = (lam & 3) * 2;

    const unsigned char* mrow0 = mask + ((size_t)b * NL + (r0g < NL ? r0g : NL - 1)) * NL;
    const unsigned char* mrow1 = mask + ((size_t)b * NL + (r1g < NL ? r1g : NL - 1)) * NL;

    // Q frags, prescaled by 1/8 (exact power of 2)
    __half2 hsc = __float2half2_rn(0.125f);
    uint4 qcf[4], qpf[4];
#pragma unroll
    for (int s = 0; s < 4; s++) {
        int c0 = s * 16 + la2;
        __half2 v;
        unsigned r[8] = {0,0,0,0,0,0,0,0};
        if (r0g < NL) {
            v = __hmul2(*(const __half2*)(QCg + r0g * 64 + c0), hsc);     r[0] = *(unsigned*)&v;
            v = __hmul2(*(const __half2*)(QCg + r0g * 64 + c0 + 8), hsc); r[2] = *(unsigned*)&v;
            v = __hmul2(*(const __half2*)(QPg + r0g * 64 + c0), hsc);     r[4] = *(unsigned*)&v;
            v = __hmul2(*(const __half2*)(QPg + r0g * 64 + c0 + 8), hsc); r[6] = *(unsigned*)&v;
        }
        if (r1g < NL) {
            v = __hmul2(*(const __half2*)(QCg + r1g * 64 + c0), hsc);     r[1] = *(unsigned*)&v;
            v = __hmul2(*(const __half2*)(QCg + r1g * 64 + c0 + 8), hsc); r[3] = *(unsigned*)&v;
            v = __hmul2(*(const __half2*)(QPg + r1g * 64 + c0), hsc);     r[5] = *(unsigned*)&v;
            v = __hmul2(*(const __half2*)(QPg + r1g * 64 + c0 + 8), hsc); r[7] = *(unsigned*)&v;
        }
        qcf[s] = make_uint4(r[0], r[1], r[2], r[3]);
        qpf[s] = make_uint4(r[4], r[5], r[6], r[7]);
    }

    float O[8][4];
#pragma unroll
    for (int n = 0; n < 8; n++)
#pragma unroll
        for (int r = 0; r < 4; r++) O[n][r] = 0.f;
    float m0 = NEG, m1 = NEG, l0 = 0.f, l1 = 0.f;

    for (int jt = 0; jt < 9; jt++) {
        int j0 = jt * 64;
        int xorv = (jt & 1) << 3;
        __syncthreads();   // staging writes vs all prev-jt reads (K,V,P,G)

        // ---- stage K tile (B-frags, k=hd, n=key) ----
        {
            int step = vhd4 >> 4, k16 = vhd4 & 15;
            unsigned boff = step * 520 + ((k16 & 7) >> 1) * 2 + (k16 >> 3);
#pragma unroll
            for (int u = 0; u < 4; u++) {
                int key = vkey + u * 16;
                int gk = j0 + key;
                uint2 kv = make_uint2(0u, 0u);
                if (gk < NL) kv = *(const uint2*)(Kg + (size_t)gk * 64 + vhd4);
                unsigned base = boff + (key >> 3) * 64 + (key & 7) * 8;
                sK[base]     = kv.x;
                sK[base + 2] = kv.y;
            }
        }
        // ---- stage V tile (B-frags, k=key, n=hd) ----
#pragma unroll
        for (int u = 0; u < 2; u++) {
            int k0 = 2 * vkey + 32 * u;
            int gk = j0 + k0;
            uint2 a = (gk < NL)     ? *(const uint2*)(Vg + (size_t)gk * 64 + vhd4)       : make_uint2(0u, 0u);
            uint2 bq = (gk + 1 < NL) ? *(const uint2*)(Vg + (size_t)(gk + 1) * 64 + vhd4) : make_uint2(0u, 0u);
            __half2 a01 = *(__half2*)&a.x,  a23 = *(__half2*)&a.y;
            __half2 b01 = *(__half2*)&bq.x, b23 = *(__half2*)&bq.y;
            unsigned o0 = pkhh(a01.x, b01.x);
            unsigned o1 = pkhh(a01.y, b01.y);
            unsigned o2 = pkhh(a23.x, b23.x);
            unsigned o3 = pkhh(a23.y, b23.y);
            int step = k0 >> 4, kk = k0 & 15;
            unsigned koff = step * 520 + ((kk & 7) >> 1) * 2 + (kk >> 3);
            sV[koff + ((vhd4 + 0) >> 3) * 64 + ((vhd4 + 0) & 7) * 8] = o0;
            sV[koff + ((vhd4 + 1) >> 3) * 64 + ((vhd4 + 1) & 7) * 8] = o1;
            sV[koff + ((vhd4 + 2) >> 3) * 64 + ((vhd4 + 2) & 7) * 8] = o2;
            sV[koff + ((vhd4 + 3) >> 3) * 64 + ((vhd4 + 3) & 7) * 8] = o3;
        }
        // ---- stage P band (circular: full 128 rows at jt=0, 64 new after) ----
        int pbase = j0 - i0 + 449;
        if (jt == 0) {
#pragma unroll
            for (int u = 0; u < 8; u++) {
                int idx = u * 256 + t;
                int c = idx >> 4, d4 = (idx & 15) * 4;
                int p = pbase + c;
                uint2 pv = make_uint2(0u, 0u);
                if ((unsigned)p < (unsigned)NP)
                    pv = *(const uint2*)(Pg + (size_t)p * 64 + d4);
                int step = d4 >> 4, k16 = d4 & 15;
                unsigned a0 = step * 1024 + (c >> 3) * 64 + ((c & 7) * 4 + ((k16 & 7) >> 1)) * 2 + (k16 >> 3);
                sP[a0]     = pv.x;
                sP[a0 + 2] = pv.y;
            }
        } else {
#pragma unroll
            for (int u = 0; u < 4; u++) {
                int idx = u * 256 + t;
                int c = 64 + (idx >> 4), d4 = (idx & 15) * 4;
                int p = pbase + c;
                uint2 pv = make_uint2(0u, 0u);
                if ((unsigned)p < (unsigned)NP)
                    pv = *(const uint2*)(Pg + (size_t)p * 64 + d4);
                int step = d4 >> 4, k16 = d4 & 15;
                unsigned a0 = step * 1024 + ((c >> 3) ^ xorv) * 64 + ((c & 7) * 4 + ((k16 & 7) >> 1)) * 2 + (k16 >> 3);
                sP[a0]     = pv.x;
                sP[a0 + 2] = pv.y;
            }
        }
        __syncthreads();

        // ---- content MMA ----
        float C[4][4];
#pragma unroll
        for (int nt = 0; nt < 4; nt++)
#pragma unroll
            for (int r = 0; r < 4; r++) C[nt][r] = 0.f;
#pragma unroll
        for (int s = 0; s < 4; s++) {
#pragma unroll
            for (int nt = 0; nt < 4; nt++) {
                uint2 bv = *(const uint2*)&sK[s * 520 + (ch * 4 + nt) * 64 + lam * 2];
                mma_f16(C[nt], qcf[s], bv);
            }
        }
        // ---- G MMA (band-pruned) + store ----
        {
            float G[5][4];
#pragma unroll
            for (int nt = 0; nt < 5; nt++)
#pragma unroll
                for (int r = 0; r < 4; r++) G[nt][r] = 0.f;
#pragma unroll
            for (int s = 0; s < 4; s++) {
#pragma unroll
                for (int nt = 0; nt < 5; nt++) {
                    int tg = (gt0 + ch * 5 + nt) ^ xorv;
                    uint2 bv = *(const uint2*)&sP[s * 1024 + tg * 64 + lam * 2];
                    mma_f16(G[nt], qpf[s], bv);
                }
            }
#pragma unroll
            for (int nt = 0; nt < 5; nt++) {
                int c0 = (gt0 + ch * 5 + nt) * 8 + la2;
                *(__half2*)&sG[gr0 * 130 + c0]       = __floats2half2_rn(G[nt][0], G[nt][1]);
                *(__half2*)&sG[(gr0 + 8) * 130 + c0] = __floats2half2_rn(G[nt][2], G[nt][3]);
            }
        }
        __syncthreads();   // G visible to both ch warps

        // ---- gather + mask -> masked scaled scores in C ----
        float mt0 = NEG, mt1 = NEG;
#pragma unroll
        for (int nt = 0; nt < 4; nt++) {
            int jjb = ch * 32 + nt * 8 + la2;
            int jc = j0 + jjb;
            float s0 = C[nt][0] + __half2float(sG[gr0 * 130 + (jjb - gr0 + 63)]);
            float s1 = C[nt][1] + __half2float(sG[gr0 * 130 + (jjb + 1 - gr0 + 63)]);
            float s2 = C[nt][2] + __half2float(sG[(gr0 + 8) * 130 + (jjb - gr0 - 8 + 63)]);
            float s3 = C[nt][3] + __half2float(sG[(gr0 + 8) * 130 + (jjb + 1 - gr0 - 8 + 63)]);
            s0 = (jc < NL && !mrow0[jc])         ? s0 : NEG;
            s1 = (jc + 1 < NL && !mrow0[jc + 1]) ? s1 : NEG;
            s2 = (jc < NL && !mrow1[jc])         ? s2 : NEG;
            s3 = (jc + 1 < NL && !mrow1[jc + 1]) ? s3 : NEG;
            C[nt][0] = s0; C[nt][1] = s1; C[nt][2] = s2; C[nt][3] = s3;
            mt0 = fmaxf(mt0, fmaxf(s0, s1));
            mt1 = fmaxf(mt1, fmaxf(s2, s3));
        }
        mt0 = fmaxf(mt0, __shfl_xor_sync(0xffffffffu, mt0, 1));
        mt0 = fmaxf(mt0, __shfl_xor_sync(0xffffffffu, mt0, 2));
        mt1 = fmaxf(mt1, __shfl_xor_sync(0xffffffffu, mt1, 1));
        mt1 = fmaxf(mt1, __shfl_xor_sync(0xffffffffu, mt1, 2));

        // ---- online softmax update ----
        float m0n = fmaxf(m0, mt0), m1n = fmaxf(m1, mt1);
        float sf0 = __expf(m0 - m0n), sf1 = __expf(m1 - m1n);
        m0 = m0n; m1 = m1n;
        float rs0 = 0.f, rs1 = 0.f;
#pragma unroll
        for (int nt = 0; nt < 4; nt++) {
            float p0 = __expf(C[nt][0] - m0);
            float p1 = __expf(C[nt][1] - m0);
            float p2 = __expf(C[nt][2] - m1);
            float p3 = __expf(C[nt][3] - m1);
            C[nt][0] = p0; C[nt][1] = p1; C[nt][2] = p2; C[nt][3] = p3;
            rs0 += p0 + p1; rs1 += p2 + p3;
        }
        rs0 += __shfl_xor_sync(0xffffffffu, rs0, 1);
        rs0 += __shfl_xor_sync(0xffffffffu, rs0, 2);
        rs1 += __shfl_xor_sync(0xffffffffu, rs1, 1);
        rs1 += __shfl_xor_sync(0xffffffffu, rs1, 2);
        l0 = l0 * sf0 + rs0;
        l1 = l1 * sf1 + rs1;
#pragma unroll
        for (int n = 0; n < 8; n++) {
            O[n][0] *= sf0; O[n][1] *= sf0;
            O[n][2] *= sf1; O[n][3] *= sf1;
        }
        // ---- AV MMA: exp(S) frags from registers ----
#pragma unroll
        for (int s2 = 0; s2 < 2; s2++) {
            uint4 af = make_uint4(
                pkh2f(C[2 * s2][0], C[2 * s2][1]),
                pkh2f(C[2 * s2][2], C[2 * s2][3]),
                pkh2f(C[2 * s2 + 1][0], C[2 * s2 + 1][1]),
                pkh2f(C[2 * s2 + 1][2], C[2 * s2 + 1][3]));
#pragma unroll
            for (int n = 0; n < 8; n++) {
                uint2 bv = *(const uint2*)&sV[(ch * 2 + s2) * 520 + n * 64 + lam * 2];
                mma_f16(O[n], af, bv);
            }
        }
    }

    // ===================== split-k merge across ch pairs =====================
    __syncthreads();
    if (ch == 1) {
#pragma unroll
        for (int n = 0; n < 8; n++) {
            int hd = n * 8 + la2;
            *(float2*)&mO[gr0 * 68 + hd]       = make_float2(O[n][0], O[n][1]);
            *(float2*)&mO[(gr0 + 8) * 68 + hd] = make_float2(O[n][2], O[n][3]);
        }
        if ((lam & 3) == 0) {
            mml[gr0 * 2 + 0] = m0; mml[gr0 * 2 + 1] = l0;
            mml[(gr0 + 8) * 2 + 0] = m1; mml[(gr0 + 8) * 2 + 1] = l1;
        }
    }
    __syncthreads();
    if (ch == 0) {
        float ma = mml[gr0 * 2 + 0], la = mml[gr0 * 2 + 1];
        float mt = fmaxf(m0, ma);
        float e0 = __expf(m0 - mt), e1 = __expf(ma - mt);
        float inv0 = 1.f / (l0 * e0 + la * e1);
        float mb = mml[(gr0 + 8) * 2 + 0], lb = mml[(gr0 + 8) * 2 + 1];
        float mtb = fmaxf(m1, mb);
        float f0 = __expf(m1 - mtb), f1 = __expf(mb - mtb);
        float inv1 = 1.f / (l1 * f0 + lb * f1);
#pragma unroll
        for (int n = 0; n < 8; n++) {
            int hd = n * 8 + la2;
            if (r0g < NL) {
                float2 oc = *(float2*)&mO[gr0 * 68 + hd];
                float2 st = make_float2((O[n][0] * e0 + oc.x * e1) * inv0,
                                        (O[n][1] * e0 + oc.y * e1) * inv0);
                *(float2*)&ctx[((size_t)b * NL + r0g) * ND + h * 64 + hd] = st;
            }
            if (r1g < NL) {
                float2 oc = *(float2*)&mO[(gr0 + 8) * 68 + hd];
                float2 st = make_float2((O[n][2] * f0 + oc.x * f1) * inv1,
                                        (O[n][3] * f0 + oc.y * f1) * inv1);
                *(float2*)&ctx[((size_t)b * NL + r1g) * ND + h * 64 + hd] = st;
            }
        }
    }
}

// ---------------------------------------------------------------------------
extern "C" void kernel_launch(void* const* d_in, const int* in_sizes, int n_in,
                              void* d_out, int out_size)
{
    const float* x     = (const float*)d_in[0];
    const float* pe    = (const float*)d_in[1];
    const unsigned char* mask = (const unsigned char*)d_in[2];
    const float* qkv_w = (const float*)d_in[3];
    const float* qkv_b = (const float*)d_in[4];
    const float* pos_w = (const float*)d_in[5];
    const float* pos_b = (const float*)d_in[6];
    const float* out_w = (const float*)d_in[7];
    const float* out_b = (const float*)d_in[8];
    const float* cbias = (const float*)d_in[9];
    const float* pbias = (const float*)d_in[10];
    float* out = (float*)d_out;

    float* ctxp = nullptr;
    cudaGetSymbolAddress((void**)&ctxp, g_CTX);

    const int M1 = NB * NL;                        // 8208
    const int GEMM_SMEM = 2 * (2120 + 2052) * 4;   // 33,376 B
    const int ATTN_SMEM = 12416 * 4;               // 49,664 B
    cudaFuncSetAttribute(gemm_f16<0>, cudaFuncAttributeMaxDynamicSharedMemorySize, GEMM_SMEM);
    cudaFuncSetAttribute(gemm_f16<1>, cudaFuncAttributeMaxDynamicSharedMemorySize, GEMM_SMEM);
    cudaFuncSetAttribute(gemm_f16<2>, cudaFuncAttributeMaxDynamicSharedMemorySize, GEMM_SMEM);
    cudaFuncSetAttribute(attn_flash, cudaFuncAttributeMaxDynamicSharedMemorySize, ATTN_SMEM);

    dim3 blk(256);
    gemm_f16<0><<<dim3(3072 / 128, (M1 + 127) / 128), blk, GEMM_SMEM>>>(
        x, qkv_w, M1, 3072, qkv_b, cbias, pbias, nullptr);
    gemm_f16<1><<<dim3(16384 / 128, 1024 / 128), blk, GEMM_SMEM>>>(
        pos_w, pe, 1024, 16384, pos_b, nullptr, nullptr, nullptr);
    attn_flash<<<dim3(9, NH, NB), blk, ATTN_SMEM>>>(mask, ctxp);
    gemm_f16<2><<<dim3(1024 / 128, (M1 + 127) / 128), blk, GEMM_SMEM>>>(
        ctxp, out_w, M1, 1024, out_b, nullptr, nullptr, out);
}

// round 14
// speedup vs baseline: 1.0826x; 1.0015x over previous
#include <cuda_runtime.h>
#include <cuda_fp16.h>
#include <math.h>

#define NB 16
#define NH 16
#define NHD 64
#define ND 1024
#define NL 513
#define NP 1024

// Scratch (allocation-free rule: __device__ globals). fp16 intermediates.
__device__ __half g_QCh[NB*NH*NL*NHD];   // q + content_bias
__device__ __half g_QPh[NB*NH*NL*NHD];   // q + position_bias
__device__ __half g_Kh [NB*NH*NL*NHD];
__device__ __half g_Vh [NB*NH*NL*NHD];
__device__ __half g_PTh[NB*NH*NP*NHD];
__device__ float  g_CTX[NB*NL*ND];       // attention output (fp32)

__device__ __forceinline__ void mma_f16(float* d, const uint4& a, const uint2& b) {
    asm volatile(
        "mma.sync.aligned.m16n8k16.row.col.f32.f16.f16.f32 "
        "{%0,%1,%2,%3}, {%4,%5,%6,%7}, {%8,%9}, {%0,%1,%2,%3};"
        : "+f"(d[0]), "+f"(d[1]), "+f"(d[2]), "+f"(d[3])
        : "r"(a.x), "r"(a.y), "r"(a.z), "r"(a.w), "r"(b.x), "r"(b.y));
}

__device__ __forceinline__ unsigned pkh2f(float x, float y) {
    __half2 h = __floats2half2_rn(x, y);
    return *(unsigned*)&h;
}
__device__ __forceinline__ unsigned pkhh(__half x, __half y) {
    __half2 h = __halves2half2(x, y);
    return *(unsigned*)&h;
}

// ---------------------------------------------------------------------------
// f16 tensor-core GEMM (m16n8k16), double-buffered BK=32, ONE barrier/chunk
// (measured-best config). EPI==1 uses transposed grid (x=M-tile, y=N-tile)
// so consecutive CTAs share the B (pe) tile -> L2 reuse.
// ---------------------------------------------------------------------------
template<int EPI>
__global__ void __launch_bounds__(256, 2)
gemm_f16(const float* __restrict__ A, const float* __restrict__ Bw,
         int M, int N,
         const float* __restrict__ bias,
         const float* __restrict__ cbias, const float* __restrict__ pbias,
         float* __restrict__ out)
{
    const int K = 1024;
    extern __shared__ unsigned gsm[];
    unsigned* sA = gsm;            // 2 x 2120
    unsigned* sB = gsm + 2 * 2120; // 2 x 2052

    int t    = threadIdx.x;
    int lane = t & 31, w = t >> 5;
    int warpM = w & 1, warpN = w >> 1;
    int m0 = (EPI == 1 ? blockIdx.x : blockIdx.y) * 128;
    int n0 = (EPI == 1 ? blockIdx.y : blockIdx.x) * 128;

    int lrow = t >> 3;
    int lkq  = t & 7;
    int kk0  = lkq * 4;
    int sstep = kk0 >> 4;
    int c16  = kk0 & 15;

    unsigned baA[4], baB[4];
#pragma unroll
    for (int u = 0; u < 4; u++) {
        int ml = lrow + u * 32;
        int mt = ml >> 4, mr = ml & 15;
        baA[u] = sstep * 1060 + mt * 132
               + ((mr & 7) * 4 + ((c16 & 7) >> 1)) * 4
               + (c16 >> 3) * 2 + (mr >> 3);
        baB[u] = sstep * 1026 + (ml >> 3) * 64
               + ((ml & 7) * 4 + ((c16 & 7) >> 1)) * 2
               + (c16 >> 3);
    }

    float acc[4][4][4];
#pragma unroll
    for (int i = 0; i < 4; i++)
#pragma unroll
        for (int j = 0; j < 4; j++)
#pragma unroll
            for (int r = 0; r < 4; r++) acc[i][j][r] = 0.f;

    float4 ra[4], rb[4];
    const float4 z4 = make_float4(0.f, 0.f, 0.f, 0.f);

#define GLOAD(KT) {                                                          \
        _Pragma("unroll")                                                    \
        for (int u = 0; u < 4; u++) {                                        \
            int gm = m0 + lrow + u * 32;                                     \
            ra[u] = (gm < M) ? *(const float4*)(A + (size_t)gm * K + (KT) + kk0) : z4; \
            rb[u] = *(const float4*)(Bw + (size_t)(n0 + lrow + u * 32) * K + (KT) + kk0); \
        } }

#define SSTORE(BI) {                                                         \
        _Pragma("unroll")                                                    \
        for (int u = 0; u < 4; u++) {                                        \
            unsigned ba = (BI) * 2120 + baA[u];                              \
            sA[ba + 0] = pkh2f(ra[u].x, ra[u].y);                            \
            sA[ba + 4] = pkh2f(ra[u].z, ra[u].w);                            \
            unsigned bb = (BI) * 2052 + baB[u];                              \
            sB[bb + 0] = pkh2f(rb[u].x, rb[u].y);                            \
            sB[bb + 2] = pkh2f(rb[u].z, rb[u].w);                            \
        } }

    GLOAD(0);
    SSTORE(0);
    __syncthreads();

    for (int c = 0; c < 32; c++) {
        int cur = c & 1;
        if (c < 31) GLOAD((c + 1) * 32);
#pragma unroll
        for (int s = 0; s < 2; s++) {
            uint4 av[4];
            uint2 bv[4];
#pragma unroll
            for (int i = 0; i < 4; i++)
                av[i] = *(const uint4*)&sA[cur * 2120 + s * 1060 + (warpM * 4 + i) * 132 + lane * 4];
#pragma unroll
            for (int j = 0; j < 4; j++)
                bv[j] = *(const uint2*)&sB[cur * 2052 + s * 1026 + (warpN * 4 + j) * 64 + lane * 2];
#pragma unroll
            for (int i = 0; i < 4; i++)
#pragma unroll
                for (int j = 0; j < 4; j++)
                    mma_f16(acc[i][j], av[i], bv[j]);
        }
        if (c < 31) SSTORE(1 - cur);
        __syncthreads();
    }
#undef GLOAD
#undef SSTORE

    int mb = m0 + warpM * 64 + (lane >> 2);
    int nb = n0 + warpN * 32 + (lane & 3) * 2;
#pragma unroll
    for (int i = 0; i < 4; i++) {
#pragma unroll
        for (int rr = 0; rr < 2; rr++) {
            int m = mb + i * 16 + rr * 8;
            if (m >= M) continue;
            if (EPI == 0) {
                int b_ = m / NL, l = m - b_ * NL;
#pragma unroll
                for (int j = 0; j < 4; j++) {
                    int n = nb + j * 8;
                    float v0 = acc[i][j][rr * 2 + 0] + bias[n];
                    float v1 = acc[i][j][rr * 2 + 1] + bias[n + 1];
                    int part = n >> 10, c1 = n & 1023;
                    int hh = c1 >> 6, hd = c1 & 63;
                    size_t o = ((((size_t)b_ * NH + hh) * NL + l) << 6) + hd;
                    if (part == 0) {
                        *(unsigned*)&g_QCh[o] = pkh2f(v0 + cbias[c1], v1 + cbias[c1 + 1]);
                        *(unsigned*)&g_QPh[o] = pkh2f(v0 + pbias[c1], v1 + pbias[c1 + 1]);
                    } else if (part == 1) {
                        *(unsigned*)&g_Kh[o] = pkh2f(v0, v1);
                    } else {
                        *(unsigned*)&g_Vh[o] = pkh2f(v0, v1);
                    }
                }
            } else if (EPI == 1) {
                float bm = bias[m];
#pragma unroll
                for (int j = 0; j < 4; j++) {
                    int n = nb + j * 8;
                    float v0 = acc[i][j][rr * 2 + 0] + bm;
                    float v1 = acc[i][j][rr * 2 + 1] + bm;
                    int bh = n >> 6, hd = n & 63;
                    *(unsigned*)&g_PTh[((((size_t)bh) << 10) + m) * 64 + hd] = pkh2f(v0, v1);
                }
            } else {
#pragma unroll
                for (int j = 0; j < 4; j++) {
                    int n = nb + j * 8;
                    float2 st;
                    st.x = acc[i][j][rr * 2 + 0] + bias[n];
                    st.y = acc[i][j][rr * 2 + 1] + bias[n + 1];
                    *(float2*)(out + (size_t)m * ND + n) = st;
                }
            }
        }
    }
}

// ---------------------------------------------------------------------------
// Flash-style fused attention (R12 known-good): register-resident S, online
// softmax, fragment-layout smem staging, circular P band (XOR tile trick).
// CTA = 64 q x (b,h); 8 warps: rg=w&3 rows, ch=w>>2 key-chunk.
// Dynamic smem 49,664 B -> 2 CTAs/SM.
// ---------------------------------------------------------------------------
__global__ void __launch_bounds__(256, 2)
attn_flash(const unsigned char* __restrict__ mask, float* __restrict__ ctx)
{
    extern __shared__ unsigned smu[];
    unsigned* sK = smu;                 // 2080 uints (4 x 520)
    unsigned* sV = smu + 2080;          // 2080 uints
    unsigned* sP = smu + 4160;          // 4096 uints (4 x 1024)
    __half*   sG = (__half*)(smu + 8256); // 64 x 130 halves (4160 uints)
    float* mO  = (float*)smu;           // merge overlay [64][68]
    float* mml = (float*)smu + 64 * 68; // [64][2]

    const float NEG = -3.4028235e38f;
    int t = threadIdx.x, lam = t & 31, w = t >> 5;
    int rg = w & 3, ch = w >> 2;
    int it = blockIdx.x, h = blockIdx.y, b = blockIdx.z;
    int i0 = it * 64;
    size_t bh = (size_t)b * NH + h;
    const __half* QCg = g_QCh + bh * NL * NHD;
    const __half* QPg = g_QPh + bh * NL * NHD;
    const __half* Kg  = g_Kh  + bh * NL * NHD;
    const __half* Vg  = g_Vh  + bh * NL * NHD;
    const __half* Pg  = g_PTh + bh * NP * NHD;

    int gr0 = rg * 16 + (lam >> 2);
    int r0g = i0 + gr0, r1g = r0g + 8;
    int gt0 = 6 - 2 * rg;
    int vkey = t >> 4;
    int vhd4 = (t & 15) * 4;
    int la2  = (lam & 3) * 2;

    const unsigned char* mrow0 = mask + ((size_t)b * NL + (r0g < NL ? r0g : NL - 1)) * NL;
    const unsigned char* mrow1 = mask + ((size_t)b * NL + (r1g < NL ? r1g : NL - 1)) * NL;

    // Q frags, prescaled by 1/8 (exact power of 2)
    __half2 hsc = __float2half2_rn(0.125f);
    uint4 qcf[4], qpf[4];
#pragma unroll
    for (int s = 0; s < 4; s++) {
        int c0 = s * 16 + la2;
        __half2 v;
        unsigned r[8] = {0,0,0,0,0,0,0,0};
        if (r0g < NL) {
            v = __hmul2(*(const __half2*)(QCg + r0g * 64 + c0), hsc);     r[0] = *(unsigned*)&v;
            v = __hmul2(*(const __half2*)(QCg + r0g * 64 + c0 + 8), hsc); r[2] = *(unsigned*)&v;
            v = __hmul2(*(const __half2*)(QPg + r0g * 64 + c0), hsc);     r[4] = *(unsigned*)&v;
            v = __hmul2(*(const __half2*)(QPg + r0g * 64 + c0 + 8), hsc); r[6] = *(unsigned*)&v;
        }
        if (r1g < NL) {
            v = __hmul2(*(const __half2*)(QCg + r1g * 64 + c0), hsc);     r[1] = *(unsigned*)&v;
            v = __hmul2(*(const __half2*)(QCg + r1g * 64 + c0 + 8), hsc); r[3] = *(unsigned*)&v;
            v = __hmul2(*(const __half2*)(QPg + r1g * 64 + c0), hsc);     r[5] = *(unsigned*)&v;
            v = __hmul2(*(const __half2*)(QPg + r1g * 64 + c0 + 8), hsc); r[7] = *(unsigned*)&v;
        }
        qcf[s] = make_uint4(r[0], r[1], r[2], r[3]);
        qpf[s] = make_uint4(r[4], r[5], r[6], r[7]);
    }

    float O[8][4];
#pragma unroll
    for (int n = 0; n < 8; n++)
#pragma unroll
        for (int r = 0; r < 4; r++) O[n][r] = 0.f;
    float m0 = NEG, m1 = NEG, l0 = 0.f, l1 = 0.f;

    for (int jt = 0; jt < 9; jt++) {
        int j0 = jt * 64;
        int xorv = (jt & 1) << 3;
        __syncthreads();   // staging writes vs all prev-jt reads (K,V,P,G)

        // ---- stage K tile (B-frags, k=hd, n=key) ----
        {
            int step = vhd4 >> 4, k16 = vhd4 & 15;
            unsigned boff = step * 520 + ((k16 & 7) >> 1) * 2 + (k16 >> 3);
#pragma unroll
            for (int u = 0; u < 4; u++) {
                int key = vkey + u * 16;
                int gk = j0 + key;
                uint2 kv = make_uint2(0u, 0u);
                if (gk < NL) kv = *(const uint2*)(Kg + (size_t)gk * 64 + vhd4);
                unsigned base = boff + (key >> 3) * 64 + (key & 7) * 8;
                sK[base]     = kv.x;
                sK[base + 2] = kv.y;
            }
        }
        // ---- stage V tile (B-frags, k=key, n=hd) ----
#pragma unroll
        for (int u = 0; u < 2; u++) {
            int k0 = 2 * vkey + 32 * u;
            int gk = j0 + k0;
            uint2 a = (gk < NL)     ? *(const uint2*)(Vg + (size_t)gk * 64 + vhd4)       : make_uint2(0u, 0u);
            uint2 bq = (gk + 1 < NL) ? *(const uint2*)(Vg + (size_t)(gk + 1) * 64 + vhd4) : make_uint2(0u, 0u);
            __half2 a01 = *(__half2*)&a.x,  a23 = *(__half2*)&a.y;
            __half2 b01 = *(__half2*)&bq.x, b23 = *(__half2*)&bq.y;
            unsigned o0 = pkhh(a01.x, b01.x);
            unsigned o1 = pkhh(a01.y, b01.y);
            unsigned o2 = pkhh(a23.x, b23.x);
            unsigned o3 = pkhh(a23.y, b23.y);
            int step = k0 >> 4, kk = k0 & 15;
            unsigned koff = step * 520 + ((kk & 7) >> 1) * 2 + (kk >> 3);
            sV[koff + ((vhd4 + 0) >> 3) * 64 + ((vhd4 + 0) & 7) * 8] = o0;
            sV[koff + ((vhd4 + 1) >> 3) * 64 + ((vhd4 + 1) & 7) * 8] = o1;
            sV[koff + ((vhd4 + 2) >> 3) * 64 + ((vhd4 + 2) & 7) * 8] = o2;
            sV[koff + ((vhd4 + 3) >> 3) * 64 + ((vhd4 + 3) & 7) * 8] = o3;
        }
        // ---- stage P band (circular: full 128 rows at jt=0, 64 new after) ----
        int pbase = j0 - i0 + 449;
        if (jt == 0) {
#pragma unroll
            for (int u = 0; u < 8; u++) {
                int idx = u * 256 + t;
                int c = idx >> 4, d4 = (idx & 15) * 4;
                int p = pbase + c;
                uint2 pv = make_uint2(0u, 0u);
                if ((unsigned)p < (unsigned)NP)
                    pv = *(const uint2*)(Pg + (size_t)p * 64 + d4);
                int step = d4 >> 4, k16 = d4 & 15;
                unsigned a0 = step * 1024 + (c >> 3) * 64 + ((c & 7) * 4 + ((k16 & 7) >> 1)) * 2 + (k16 >> 3);
                sP[a0]     = pv.x;
                sP[a0 + 2] = pv.y;
            }
        } else {
#pragma unroll
            for (int u = 0; u < 4; u++) {
                int idx = u * 256 + t;
                int c = 64 + (idx >> 4), d4 = (idx & 15) * 4;
                int p = pbase + c;
                uint2 pv = make_uint2(0u, 0u);
                if ((unsigned)p < (unsigned)NP)
                    pv = *(const uint2*)(Pg + (size_t)p * 64 + d4);
                int step = d4 >> 4, k16 = d4 & 15;
                unsigned a0 = step * 1024 + ((c >> 3) ^ xorv) * 64 + ((c & 7) * 4 + ((k16 & 7) >> 1)) * 2 + (k16 >> 3);
                sP[a0]     = pv.x;
                sP[a0 + 2] = pv.y;
            }
        }
        __syncthreads();

        // ---- content MMA ----
        float C[4][4];
#pragma unroll
        for (int nt = 0; nt < 4; nt++)
#pragma unroll
            for (int r = 0; r < 4; r++) C[nt][r] = 0.f;
#pragma unroll
        for (int s = 0; s < 4; s++) {
#pragma unroll
            for (int nt = 0; nt < 4; nt++) {
                uint2 bv = *(const uint2*)&sK[s * 520 + (ch * 4 + nt) * 64 + lam * 2];
                mma_f16(C[nt], qcf[s], bv);
            }
        }
        // ---- G MMA (band-pruned) + store ----
        {
            float G[5][4];
#pragma unroll
            for (int nt = 0; nt < 5; nt++)
#pragma unroll
                for (int r = 0; r < 4; r++) G[nt][r] = 0.f;
#pragma unroll
            for (int s = 0; s < 4; s++) {
#pragma unroll
                for (int nt = 0; nt < 5; nt++) {
                    int tg = (gt0 + ch * 5 + nt) ^ xorv;
                    uint2 bv = *(const uint2*)&sP[s * 1024 + tg * 64 + lam * 2];
                    mma_f16(G[nt], qpf[s], bv);
                }
            }
#pragma unroll
            for (int nt = 0; nt < 5; nt++) {
                int c0 = (gt0 + ch * 5 + nt) * 8 + la2;
                *(__half2*)&sG[gr0 * 130 + c0]       = __floats2half2_rn(G[nt][0], G[nt][1]);
                *(__half2*)&sG[(gr0 + 8) * 130 + c0] = __floats2half2_rn(G[nt][2], G[nt][3]);
            }
        }
        __syncthreads();   // G visible to both ch warps

        // ---- gather + mask -> masked scaled scores in C ----
        float mt0 = NEG, mt1 = NEG;
#pragma unroll
        for (int nt = 0; nt < 4; nt++) {
            int jjb = ch * 32 + nt * 8 + la2;
            int jc = j0 + jjb;
            float s0 = C[nt][0] + __half2float(sG[gr0 * 130 + (jjb - gr0 + 63)]);
            float s1 = C[nt][1] + __half2float(sG[gr0 * 130 + (jjb + 1 - gr0 + 63)]);
            float s2 = C[nt][2] + __half2float(sG[(gr0 + 8) * 130 + (jjb - gr0 - 8 + 63)]);
            float s3 = C[nt][3] + __half2float(sG[(gr0 + 8) * 130 + (jjb + 1 - gr0 - 8 + 63)]);
            s0 = (jc < NL && !mrow0[jc])         ? s0 : NEG;
            s1 = (jc + 1 < NL && !mrow0[jc + 1]) ? s1 : NEG;
            s2 = (jc < NL && !mrow1[jc])         ? s2 : NEG;
            s3 = (jc + 1 < NL && !mrow1[jc + 1]) ? s3 : NEG;
            C[nt][0] = s0; C[nt][1] = s1; C[nt][2] = s2; C[nt][3] = s3;
            mt0 = fmaxf(mt0, fmaxf(s0, s1));
            mt1 = fmaxf(mt1, fmaxf(s2, s3));
        }
        mt0 = fmaxf(mt0, __shfl_xor_sync(0xffffffffu, mt0, 1));
        mt0 = fmaxf(mt0, __shfl_xor_sync(0xffffffffu, mt0, 2));
        mt1 = fmaxf(mt1, __shfl_xor_sync(0xffffffffu, mt1, 1));
        mt1 = fmaxf(mt1, __shfl_xor_sync(0xffffffffu, mt1, 2));

        // ---- online softmax update ----
        float m0n = fmaxf(m0, mt0), m1n = fmaxf(m1, mt1);
        float sf0 = __expf(m0 - m0n), sf1 = __expf(m1 - m1n);
        m0 = m0n; m1 = m1n;
        float rs0 = 0.f, rs1 = 0.f;
#pragma unroll
        for (int nt = 0; nt < 4; nt++) {
            float p0 = __expf(C[nt][0] - m0);
            float p1 = __expf(C[nt][1] - m0);
            float p2 = __expf(C[nt][2] - m1);
            float p3 = __expf(C[nt][3] - m1);
            C[nt][0] = p0; C[nt][1] = p1; C[nt][2] = p2; C[nt][3] = p3;
            rs0 += p0 + p1; rs1 += p2 + p3;
        }
        rs0 += __shfl_xor_sync(0xffffffffu, rs0, 1);
        rs0 += __shfl_xor_sync(0xffffffffu, rs0, 2);
        rs1 += __shfl_xor_sync(0xffffffffu, rs1, 1);
        rs1 += __shfl_xor_sync(0xffffffffu, rs1, 2);
        l0 = l0 * sf0 + rs0;
        l1 = l1 * sf1 + rs1;
#pragma unroll
        for (int n = 0; n < 8; n++) {
            O[n][0] *= sf0; O[n][1] *= sf0;
            O[n][2] *= sf1; O[n][3] *= sf1;
        }
        // ---- AV MMA: exp(S) frags from registers ----
#pragma unroll
        for (int s2 = 0; s2 < 2; s2++) {
            uint4 af = make_uint4(
                pkh2f(C[2 * s2][0], C[2 * s2][1]),
                pkh2f(C[2 * s2][2], C[2 * s2][3]),
                pkh2f(C[2 * s2 + 1][0], C[2 * s2 + 1][1]),
                pkh2f(C[2 * s2 + 1][2], C[2 * s2 + 1][3]));
#pragma unroll
            for (int n = 0; n < 8; n++) {
                uint2 bv = *(const uint2*)&sV[(ch * 2 + s2) * 520 + n * 64 + lam * 2];
                mma_f16(O[n], af, bv);
            }
        }
    }

    // ===================== split-k merge across ch pairs =====================
    __syncthreads();
    if (ch == 1) {
#pragma unroll
        for (int n = 0; n < 8; n++) {
            int hd = n * 8 + la2;
            *(float2*)&mO[gr0 * 68 + hd]       = make_float2(O[n][0], O[n][1]);
            *(float2*)&mO[(gr0 + 8) * 68 + hd] = make_float2(O[n][2], O[n][3]);
        }
        if ((lam & 3) == 0) {
            mml[gr0 * 2 + 0] = m0; mml[gr0 * 2 + 1] = l0;
            mml[(gr0 + 8) * 2 + 0] = m1; mml[(gr0 + 8) * 2 + 1] = l1;
        }
    }
    __syncthreads();
    if (ch == 0) {
        float ma = mml[gr0 * 2 + 0], la = mml[gr0 * 2 + 1];
        float mt = fmaxf(m0, ma);
        float e0 = __expf(m0 - mt), e1 = __expf(ma - mt);
        float inv0 = 1.f / (l0 * e0 + la * e1);
        float mb = mml[(gr0 + 8) * 2 + 0], lb = mml[(gr0 + 8) * 2 + 1];
        float mtb = fmaxf(m1, mb);
        float f0 = __expf(m1 - mtb), f1 = __expf(mb - mtb);
        float inv1 = 1.f / (l1 * f0 + lb * f1);
#pragma unroll
        for (int n = 0; n < 8; n++) {
            int hd = n * 8 + la2;
            if (r0g < NL) {
                float2 oc = *(float2*)&mO[gr0 * 68 + hd];
                float2 st = make_float2((O[n][0] * e0 + oc.x * e1) * inv0,
                                        (O[n][1] * e0 + oc.y * e1) * inv0);
                *(float2*)&ctx[((size_t)b * NL + r0g) * ND + h * 64 + hd] = st;
            }
            if (r1g < NL) {
                float2 oc = *(float2*)&mO[(gr0 + 8) * 68 + hd];
                float2 st = make_float2((O[n][2] * f0 + oc.x * f1) * inv1,
                                        (O[n][3] * f0 + oc.y * f1) * inv1);
                *(float2*)&ctx[((size_t)b * NL + r1g) * ND + h * 64 + hd] = st;
            }
        }
    }
}

// ---------------------------------------------------------------------------
extern "C" void kernel_launch(void* const* d_in, const int* in_sizes, int n_in,
                              void* d_out, int out_size)
{
    const float* x     = (const float*)d_in[0];
    const float* pe    = (const float*)d_in[1];
    const unsigned char* mask = (const unsigned char*)d_in[2];
    const float* qkv_w = (const float*)d_in[3];
    const float* qkv_b = (const float*)d_in[4];
    const float* pos_w = (const float*)d_in[5];
    const float* pos_b = (const float*)d_in[6];
    const float* out_w = (const float*)d_in[7];
    const float* out_b = (const float*)d_in[8];
    const float* cbias = (const float*)d_in[9];
    const float* pbias = (const float*)d_in[10];
    float* out = (float*)d_out;

    float* ctxp = nullptr;
    cudaGetSymbolAddress((void**)&ctxp, g_CTX);

    const int M1 = NB * NL;                        // 8208
    const int GEMM_SMEM = 2 * (2120 + 2052) * 4;   // 33,376 B
    const int ATTN_SMEM = 12416 * 4;               // 49,664 B
    cudaFuncSetAttribute(gemm_f16<0>, cudaFuncAttributeMaxDynamicSharedMemorySize, GEMM_SMEM);
    cudaFuncSetAttribute(gemm_f16<1>, cudaFuncAttributeMaxDynamicSharedMemorySize, GEMM_SMEM);
    cudaFuncSetAttribute(gemm_f16<2>, cudaFuncAttributeMaxDynamicSharedMemorySize, GEMM_SMEM);
    cudaFuncSetAttribute(attn_flash, cudaFuncAttributeMaxDynamicSharedMemorySize, ATTN_SMEM);

    dim3 blk(256);
    gemm_f16<0><<<dim3(3072 / 128, (M1 + 127) / 128), blk, GEMM_SMEM>>>(
        x, qkv_w, M1, 3072, qkv_b, cbias, pbias, nullptr);
    // EPI==1: transposed grid (x = M-tiles, y = N-tiles) for pe L2 reuse
    gemm_f16<1><<<dim3(1024 / 128, 16384 / 128), blk, GEMM_SMEM>>>(
        pos_w, pe, 1024, 16384, pos_b, nullptr, nullptr, nullptr);
    attn_flash<<<dim3(9, NH, NB), blk, ATTN_SMEM>>>(mask, ctxp);
    gemm_f16<2><<<dim3(1024 / 128, (M1 + 127) / 128), blk, GEMM_SMEM>>>(
        ctxp, out_w, M1, 1024, out_b, nullptr, nullptr, out);
}

// round 15
// speedup vs baseline: 1.0936x; 1.0101x over previous
#include <cuda_runtime.h>
#include <cuda_fp16.h>
#include <math.h>

#define NB 16
#define NH 16
#define NHD 64
#define ND 1024
#define NL 513
#define NP 1024

// Scratch (allocation-free rule: __device__ globals). fp16 intermediates.
__device__ __half g_QCh[NB*NH*NL*NHD];   // q + content_bias
__device__ __half g_QPh[NB*NH*NL*NHD];   // q + position_bias
__device__ __half g_Kh [NB*NH*NL*NHD];
__device__ __half g_Vh [NB*NH*NL*NHD];
__device__ __half g_PTh[NB*NH*NP*NHD];
__device__ float  g_CTX[NB*NL*ND];       // attention output (fp32)

__device__ __forceinline__ void mma_f16(float* d, const uint4& a, const uint2& b) {
    asm volatile(
        "mma.sync.aligned.m16n8k16.row.col.f32.f16.f16.f32 "
        "{%0,%1,%2,%3}, {%4,%5,%6,%7}, {%8,%9}, {%0,%1,%2,%3};"
        : "+f"(d[0]), "+f"(d[1]), "+f"(d[2]), "+f"(d[3])
        : "r"(a.x), "r"(a.y), "r"(a.z), "r"(a.w), "r"(b.x), "r"(b.y));
}

__device__ __forceinline__ unsigned pkh2f(float x, float y) {
    __half2 h = __floats2half2_rn(x, y);
    return *(unsigned*)&h;
}
__device__ __forceinline__ unsigned pkhh(__half x, __half y) {
    __half2 h = __halves2half2(x, y);
    return *(unsigned*)&h;
}

// ---------------------------------------------------------------------------
// Fused QKV + POS projections in ONE grid (independent work; merged tails).
// bid < 1560: QKV GEMM tile (n-fastest, shares A panel across consecutive bids)
// bid >= 1560: POS GEMM tile (m-fastest, shares pe B panel)
// Mainloop: f16 m16n8k16, double-buffered BK=32, one barrier/chunk.
// ---------------------------------------------------------------------------
__global__ void __launch_bounds__(256, 2)
gemm_fused(const float* __restrict__ x, const float* __restrict__ qw,
           const float* __restrict__ qb, const float* __restrict__ cb,
           const float* __restrict__ pbv,
           const float* __restrict__ pw, const float* __restrict__ pe,
           const float* __restrict__ posb)
{
    const int K = 1024;
    extern __shared__ unsigned gsm[];
    unsigned* sA = gsm;            // 2 x 2120
    unsigned* sB = gsm + 2 * 2120; // 2 x 2052

    int bid = blockIdx.x;
    int epi, m0, n0, M;
    const float *A, *Bw;
    if (bid < 1560) {
        epi = 0; m0 = (bid / 24) * 128; n0 = (bid % 24) * 128;
        A = x; Bw = qw; M = NB * NL;
    } else {
        int i2 = bid - 1560;
        epi = 1; m0 = (i2 % 8) * 128; n0 = (i2 / 8) * 128;
        A = pw; Bw = pe; M = 1024;
    }

    int t    = threadIdx.x;
    int lane = t & 31, w = t >> 5;
    int warpM = w & 1, warpN = w >> 1;

    int lrow = t >> 3;
    int lkq  = t & 7;
    int kk0  = lkq * 4;
    int sstep = kk0 >> 4;
    int c16  = kk0 & 15;

    unsigned baA[4], baB[4];
#pragma unroll
    for (int u = 0; u < 4; u++) {
        int ml = lrow + u * 32;
        int mt = ml >> 4, mr = ml & 15;
        baA[u] = sstep * 1060 + mt * 132
               + ((mr & 7) * 4 + ((c16 & 7) >> 1)) * 4
               + (c16 >> 3) * 2 + (mr >> 3);
        baB[u] = sstep * 1026 + (ml >> 3) * 64
               + ((ml & 7) * 4 + ((c16 & 7) >> 1)) * 2
               + (c16 >> 3);
    }

    float acc[4][4][4];
#pragma unroll
    for (int i = 0; i < 4; i++)
#pragma unroll
        for (int j = 0; j < 4; j++)
#pragma unroll
            for (int r = 0; r < 4; r++) acc[i][j][r] = 0.f;

    float4 ra[4], rb[4];
    const float4 z4 = make_float4(0.f, 0.f, 0.f, 0.f);

#define GLOADF(KT) {                                                         \
        _Pragma("unroll")                                                    \
        for (int u = 0; u < 4; u++) {                                        \
            int gm = m0 + lrow + u * 32;                                     \
            ra[u] = (gm < M) ? *(const float4*)(A + (size_t)gm * K + (KT) + kk0) : z4; \
            rb[u] = *(const float4*)(Bw + (size_t)(n0 + lrow + u * 32) * K + (KT) + kk0); \
        } }

#define SSTOREF(BI) {                                                        \
        _Pragma("unroll")                                                    \
        for (int u = 0; u < 4; u++) {                                        \
            unsigned ba = (BI) * 2120 + baA[u];                              \
            sA[ba + 0] = pkh2f(ra[u].x, ra[u].y);                            \
            sA[ba + 4] = pkh2f(ra[u].z, ra[u].w);                            \
            unsigned bb = (BI) * 2052 + baB[u];                              \
            sB[bb + 0] = pkh2f(rb[u].x, rb[u].y);                            \
            sB[bb + 2] = pkh2f(rb[u].z, rb[u].w);                            \
        } }

    GLOADF(0);
    SSTOREF(0);
    __syncthreads();

    for (int c = 0; c < 32; c++) {
        int cur = c & 1;
        if (c < 31) GLOADF((c + 1) * 32);
#pragma unroll
        for (int s = 0; s < 2; s++) {
            uint4 av[4];
            uint2 bv[4];
#pragma unroll
            for (int i = 0; i < 4; i++)
                av[i] = *(const uint4*)&sA[cur * 2120 + s * 1060 + (warpM * 4 + i) * 132 + lane * 4];
#pragma unroll
            for (int j = 0; j < 4; j++)
                bv[j] = *(const uint2*)&sB[cur * 2052 + s * 1026 + (warpN * 4 + j) * 64 + lane * 2];
#pragma unroll
            for (int i = 0; i < 4; i++)
#pragma unroll
                for (int j = 0; j < 4; j++)
                    mma_f16(acc[i][j], av[i], bv[j]);
        }
        if (c < 31) SSTOREF(1 - cur);
        __syncthreads();
    }
#undef GLOADF
#undef SSTOREF

    int mb = m0 + warpM * 64 + (lane >> 2);
    int nb = n0 + warpN * 32 + (lane & 3) * 2;
#pragma unroll
    for (int i = 0; i < 4; i++) {
#pragma unroll
        for (int rr = 0; rr < 2; rr++) {
            int m = mb + i * 16 + rr * 8;
            if (m >= M) continue;
            if (epi == 0) {
                int b_ = m / NL, l = m - b_ * NL;
#pragma unroll
                for (int j = 0; j < 4; j++) {
                    int n = nb + j * 8;
                    float v0 = acc[i][j][rr * 2 + 0] + qb[n];
                    float v1 = acc[i][j][rr * 2 + 1] + qb[n + 1];
                    int part = n >> 10, c1 = n & 1023;
                    int hh = c1 >> 6, hd = c1 & 63;
                    size_t o = ((((size_t)b_ * NH + hh) * NL + l) << 6) + hd;
                    if (part == 0) {
                        *(unsigned*)&g_QCh[o] = pkh2f(v0 + cb[c1], v1 + cb[c1 + 1]);
                        *(unsigned*)&g_QPh[o] = pkh2f(v0 + pbv[c1], v1 + pbv[c1 + 1]);
                    } else if (part == 1) {
                        *(unsigned*)&g_Kh[o] = pkh2f(v0, v1);
                    } else {
                        *(unsigned*)&g_Vh[o] = pkh2f(v0, v1);
                    }
                }
            } else {
                float bm = posb[m];
#pragma unroll
                for (int j = 0; j < 4; j++) {
                    int n = nb + j * 8;
                    float v0 = acc[i][j][rr * 2 + 0] + bm;
                    float v1 = acc[i][j][rr * 2 + 1] + bm;
                    int bh = n >> 6, hd = n & 63;
                    *(unsigned*)&g_PTh[((((size_t)bh) << 10) + m) * 64 + hd] = pkh2f(v0, v1);
                }
            }
        }
    }
}

// ---------------------------------------------------------------------------
// f16 tensor-core GEMM for the output projection (EPI==2 path of the old
// template; unchanged measured-best config).
// ---------------------------------------------------------------------------
__global__ void __launch_bounds__(256, 2)
gemm_out(const float* __restrict__ A_unused, const float* __restrict__ Bw,
         int M, int N, const float* __restrict__ bias, float* __restrict__ out)
{
    const int K = 1024;
    extern __shared__ unsigned gsm[];
    unsigned* sA = gsm;
    unsigned* sB = gsm + 2 * 2120;
    const float* A = (const float*)g_CTX;

    int t    = threadIdx.x;
    int lane = t & 31, w = t >> 5;
    int warpM = w & 1, warpN = w >> 1;
    int m0 = blockIdx.y * 128, n0 = blockIdx.x * 128;

    int lrow = t >> 3;
    int lkq  = t & 7;
    int kk0  = lkq * 4;
    int sstep = kk0 >> 4;
    int c16  = kk0 & 15;

    unsigned baA[4], baB[4];
#pragma unroll
    for (int u = 0; u < 4; u++) {
        int ml = lrow + u * 32;
        int mt = ml >> 4, mr = ml & 15;
        baA[u] = sstep * 1060 + mt * 132
               + ((mr & 7) * 4 + ((c16 & 7) >> 1)) * 4
               + (c16 >> 3) * 2 + (mr >> 3);
        baB[u] = sstep * 1026 + (ml >> 3) * 64
               + ((ml & 7) * 4 + ((c16 & 7) >> 1)) * 2
               + (c16 >> 3);
    }

    float acc[4][4][4];
#pragma unroll
    for (int i = 0; i < 4; i++)
#pragma unroll
        for (int j = 0; j < 4; j++)
#pragma unroll
            for (int r = 0; r < 4; r++) acc[i][j][r] = 0.f;

    float4 ra[4], rb[4];
    const float4 z4 = make_float4(0.f, 0.f, 0.f, 0.f);

#define GLOADO(KT) {                                                         \
        _Pragma("unroll")                                                    \
        for (int u = 0; u < 4; u++) {                                        \
            int gm = m0 + lrow + u * 32;                                     \
            ra[u] = (gm < M) ? *(const float4*)(A + (size_t)gm * K + (KT) + kk0) : z4; \
            rb[u] = *(const float4*)(Bw + (size_t)(n0 + lrow + u * 32) * K + (KT) + kk0); \
        } }

#define SSTOREO(BI) {                                                        \
        _Pragma("unroll")                                                    \
        for (int u = 0; u < 4; u++) {                                        \
            unsigned ba = (BI) * 2120 + baA[u];                              \
            sA[ba + 0] = pkh2f(ra[u].x, ra[u].y);                            \
            sA[ba + 4] = pkh2f(ra[u].z, ra[u].w);                            \
            unsigned bb = (BI) * 2052 + baB[u];                              \
            sB[bb + 0] = pkh2f(rb[u].x, rb[u].y);                            \
            sB[bb + 2] = pkh2f(rb[u].z, rb[u].w);                            \
        } }

    GLOADO(0);
    SSTOREO(0);
    __syncthreads();

    for (int c = 0; c < 32; c++) {
        int cur = c & 1;
        if (c < 31) GLOADO((c + 1) * 32);
#pragma unroll
        for (int s = 0; s < 2; s++) {
            uint4 av[4];
            uint2 bv[4];
#pragma unroll
            for (int i = 0; i < 4; i++)
                av[i] = *(const uint4*)&sA[cur * 2120 + s * 1060 + (warpM * 4 + i) * 132 + lane * 4];
#pragma unroll
            for (int j = 0; j < 4; j++)
                bv[j] = *(const uint2*)&sB[cur * 2052 + s * 1026 + (warpN * 4 + j) * 64 + lane * 2];
#pragma unroll
            for (int i = 0; i < 4; i++)
#pragma unroll
                for (int j = 0; j < 4; j++)
                    mma_f16(acc[i][j], av[i], bv[j]);
        }
        if (c < 31) SSTOREO(1 - cur);
        __syncthreads();
    }
#undef GLOADO
#undef SSTOREO

    int mb = m0 + warpM * 64 + (lane >> 2);
    int nb = n0 + warpN * 32 + (lane & 3) * 2;
#pragma unroll
    for (int i = 0; i < 4; i++) {
#pragma unroll
        for (int rr = 0; rr < 2; rr++) {
            int m = mb + i * 16 + rr * 8;
            if (m >= M) continue;
#pragma unroll
            for (int j = 0; j < 4; j++) {
                int n = nb + j * 8;
                float2 st;
                st.x = acc[i][j][rr * 2 + 0] + bias[n];
                st.y = acc[i][j][rr * 2 + 1] + bias[n + 1];
                *(float2*)(out + (size_t)m * ND + n) = st;
            }
        }
    }
}

// ---------------------------------------------------------------------------
// Flash-style fused attention (R12 known-good + V-store bank rotation).
// CTA = 64 q x (b,h); 8 warps: rg=w&3 rows, ch=w>>2 key-chunk.
// Dynamic smem 49,664 B -> 2 CTAs/SM.
// ---------------------------------------------------------------------------
__global__ void __launch_bounds__(256, 2)
attn_flash(const unsigned char* __restrict__ mask, float* __restrict__ ctx)
{
    extern __shared__ unsigned smu[];
    unsigned* sK = smu;                 // 2080 uints (4 x 520)
    unsigned* sV = smu + 2080;          // 2080 uints
    unsigned* sP = smu + 4160;          // 4096 uints (4 x 1024)
    __half*   sG = (__half*)(smu + 8256); // 64 x 130 halves (4160 uints)
    float* mO  = (float*)smu;           // merge overlay [64][68]
    float* mml = (float*)smu + 64 * 68; // [64][2]

    const float NEG = -3.4028235e38f;
    int t = threadIdx.x, lam = t & 31, w = t >> 5;
    int rg = w & 3, ch = w >> 2;
    int it = blockIdx.x, h = blockIdx.y, b = blockIdx.z;
    int i0 = it * 64;
    size_t bh = (size_t)b * NH + h;
    const __half* QCg = g_QCh + bh * NL * NHD;
    const __half* QPg = g_QPh + bh * NL * NHD;
    const __half* Kg  = g_Kh  + bh * NL * NHD;
    const __half* Vg  = g_Vh  + bh * NL * NHD;
    const __half* Pg  = g_PTh + bh * NP * NHD;

    int gr0 = rg * 16 + (lam >> 2);
    int r0g = i0 + gr0, r1g = r0g + 8;
    int gt0 = 6 - 2 * rg;
    int vkey = t >> 4;
    int vhd4 = (t & 15) * 4;
    int la2  = (lam & 3) * 2;

    const unsigned char* mrow0 = mask + ((size_t)b * NL + (r0g < NL ? r0g : NL - 1)) * NL;
    const unsigned char* mrow1 = mask + ((size_t)b * NL + (r1g < NL ? r1g : NL - 1)) * NL;

    // Q frags, prescaled by 1/8 (exact power of 2)
    __half2 hsc = __float2half2_rn(0.125f);
    uint4 qcf[4], qpf[4];
#pragma unroll
    for (int s = 0; s < 4; s++) {
        int c0 = s * 16 + la2;
        __half2 v;
        unsigned r[8] = {0,0,0,0,0,0,0,0};
        if (r0g < NL) {
            v = __hmul2(*(const __half2*)(QCg + r0g * 64 + c0), hsc);     r[0] = *(unsigned*)&v;
            v = __hmul2(*(const __half2*)(QCg + r0g * 64 + c0 + 8), hsc); r[2] = *(unsigned*)&v;
            v = __hmul2(*(const __half2*)(QPg + r0g * 64 + c0), hsc);     r[4] = *(unsigned*)&v;
            v = __hmul2(*(const __half2*)(QPg + r0g * 64 + c0 + 8), hsc); r[6] = *(unsigned*)&v;
        }
        if (r1g < NL) {
            v = __hmul2(*(const __half2*)(QCg + r1g * 64 + c0), hsc);     r[1] = *(unsigned*)&v;
            v = __hmul2(*(const __half2*)(QCg + r1g * 64 + c0 + 8), hsc); r[3] = *(unsigned*)&v;
            v = __hmul2(*(const __half2*)(QPg + r1g * 64 + c0), hsc);     r[5] = *(unsigned*)&v;
            v = __hmul2(*(const __half2*)(QPg + r1g * 64 + c0 + 8), hsc); r[7] = *(unsigned*)&v;
        }
        qcf[s] = make_uint4(r[0], r[1], r[2], r[3]);
        qpf[s] = make_uint4(r[4], r[5], r[6], r[7]);
    }

    float O[8][4];
#pragma unroll
    for (int n = 0; n < 8; n++)
#pragma unroll
        for (int r = 0; r < 4; r++) O[n][r] = 0.f;
    float m0 = NEG, m1 = NEG, l0 = 0.f, l1 = 0.f;

    for (int jt = 0; jt < 9; jt++) {
        int j0 = jt * 64;
        int xorv = (jt & 1) << 3;
        __syncthreads();   // staging writes vs all prev-jt reads (K,V,P,G)

        // ---- stage K tile (B-frags, k=hd, n=key) ----
        {
            int step = vhd4 >> 4, k16 = vhd4 & 15;
            unsigned boff = step * 520 + ((k16 & 7) >> 1) * 2 + (k16 >> 3);
#pragma unroll
            for (int u = 0; u < 4; u++) {
                int key = vkey + u * 16;
                int gk = j0 + key;
                uint2 kv = make_uint2(0u, 0u);
                if (gk < NL) kv = *(const uint2*)(Kg + (size_t)gk * 64 + vhd4);
                unsigned base = boff + (key >> 3) * 64 + (key & 7) * 8;
                sK[base]     = kv.x;
                sK[base + 2] = kv.y;
            }
        }
        // ---- stage V tile (B-frags, k=key, n=hd); store order rotated by
        //      lam&3 so concurrent stores spread over 8 banks (4-way max) ----
#pragma unroll
        for (int u = 0; u < 2; u++) {
            int k0 = 2 * vkey + 32 * u;
            int gk = j0 + k0;
            uint2 a = (gk < NL)     ? *(const uint2*)(Vg + (size_t)gk * 64 + vhd4)       : make_uint2(0u, 0u);
            uint2 bq = (gk + 1 < NL) ? *(const uint2*)(Vg + (size_t)(gk + 1) * 64 + vhd4) : make_uint2(0u, 0u);
            __half2 a01 = *(__half2*)&a.x,  a23 = *(__half2*)&a.y;
            __half2 b01 = *(__half2*)&bq.x, b23 = *(__half2*)&bq.y;
            unsigned o0 = pkhh(a01.x, b01.x);
            unsigned o1 = pkhh(a01.y, b01.y);
            unsigned o2 = pkhh(a23.x, b23.x);
            unsigned o3 = pkhh(a23.y, b23.y);
            int step = k0 >> 4, kk = k0 & 15;
            unsigned koff = step * 520 + ((kk & 7) >> 1) * 2 + (kk >> 3)
                          + (vhd4 >> 3) * 64 + (vhd4 & 4) * 8;
            int rot = lam & 3;
#pragma unroll
            for (int e4 = 0; e4 < 4; e4++) {
                int e = (e4 + rot) & 3;
                unsigned v = (e == 0) ? o0 : (e == 1) ? o1 : (e == 2) ? o2 : o3;
                sV[koff + e * 8] = v;
            }
        }
        // ---- stage P band (circular: full 128 rows at jt=0, 64 new after) ----
        int pbase = j0 - i0 + 449;
        if (jt == 0) {
#pragma unroll
            for (int u = 0; u < 8; u++) {
                int idx = u * 256 + t;
                int c = idx >> 4, d4 = (idx & 15) * 4;
                int p = pbase + c;
                uint2 pv = make_uint2(0u, 0u);
                if ((unsigned)p < (unsigned)NP)
                    pv = *(const uint2*)(Pg + (size_t)p * 64 + d4);
                int step = d4 >> 4, k16 = d4 & 15;
                unsigned a0 = step * 1024 + (c >> 3) * 64 + ((c & 7) * 4 + ((k16 & 7) >> 1)) * 2 + (k16 >> 3);
                sP[a0]     = pv.x;
                sP[a0 + 2] = pv.y;
            }
        } else {
#pragma unroll
            for (int u = 0; u < 4; u++) {
                int idx = u * 256 + t;
                int c = 64 + (idx >> 4), d4 = (idx & 15) * 4;
                int p = pbase + c;
                uint2 pv = make_uint2(0u, 0u);
                if ((unsigned)p < (unsigned)NP)
                    pv = *(const uint2*)(Pg + (size_t)p * 64 + d4);
                int step = d4 >> 4, k16 = d4 & 15;
                unsigned a0 = step * 1024 + ((c >> 3) ^ xorv) * 64 + ((c & 7) * 4 + ((k16 & 7) >> 1)) * 2 + (k16 >> 3);
                sP[a0]     = pv.x;
                sP[a0 + 2] = pv.y;
            }
        }
        __syncthreads();

        // ---- content MMA ----
        float C[4][4];
#pragma unroll
        for (int nt = 0; nt < 4; nt++)
#pragma unroll
            for (int r = 0; r < 4; r++) C[nt][r] = 0.f;
#pragma unroll
        for (int s = 0; s < 4; s++) {
#pragma unroll
            for (int nt = 0; nt < 4; nt++) {
                uint2 bv = *(const uint2*)&sK[s * 520 + (ch * 4 + nt) * 64 + lam * 2];
                mma_f16(C[nt], qcf[s], bv);
            }
        }
        // ---- G MMA (band-pruned) + store ----
        {
            float G[5][4];
#pragma unroll
            for (int nt = 0; nt < 5; nt++)
#pragma unroll
                for (int r = 0; r < 4; r++) G[nt][r] = 0.f;
#pragma unroll
            for (int s = 0; s < 4; s++) {
#pragma unroll
                for (int nt = 0; nt < 5; nt++) {
                    int tg = (gt0 + ch * 5 + nt) ^ xorv;
                    uint2 bv = *(const uint2*)&sP[s * 1024 + tg * 64 + lam * 2];
                    mma_f16(G[nt], qpf[s], bv);
                }
            }
#pragma unroll
            for (int nt = 0; nt < 5; nt++) {
                int c0 = (gt0 + ch * 5 + nt) * 8 + la2;
                *(__half2*)&sG[gr0 * 130 + c0]       = __floats2half2_rn(G[nt][0], G[nt][1]);
                *(__half2*)&sG[(gr0 + 8) * 130 + c0] = __floats2half2_rn(G[nt][2], G[nt][3]);
            }
        }
        __syncthreads();   // G visible to both ch warps

        // ---- gather + mask -> masked scaled scores in C ----
        float mt0 = NEG, mt1 = NEG;
#pragma unroll
        for (int nt = 0; nt < 4; nt++) {
            int jjb = ch * 32 + nt * 8 + la2;
            int jc = j0 + jjb;
            float s0 = C[nt][0] + __half2float(sG[gr0 * 130 + (jjb - gr0 + 63)]);
            float s1 = C[nt][1] + __half2float(sG[gr0 * 130 + (jjb + 1 - gr0 + 63)]);
            float s2 = C[nt][2] + __half2float(sG[(gr0 + 8) * 130 + (jjb - gr0 - 8 + 63)]);
            float s3 = C[nt][3] + __half2float(sG[(gr0 + 8) * 130 + (jjb + 1 - gr0 - 8 + 63)]);
            s0 = (jc < NL && !mrow0[jc])         ? s0 : NEG;
            s1 = (jc + 1 < NL && !mrow0[jc + 1]) ? s1 : NEG;
            s2 = (jc < NL && !mrow1[jc])         ? s2 : NEG;
            s3 = (jc + 1 < NL && !mrow1[jc + 1]) ? s3 : NEG;
            C[nt][0] = s0; C[nt][1] = s1; C[nt][2] = s2; C[nt][3] = s3;
            mt0 = fmaxf(mt0, fmaxf(s0, s1));
            mt1 = fmaxf(mt1, fmaxf(s2, s3));
        }
        mt0 = fmaxf(mt0, __shfl_xor_sync(0xffffffffu, mt0, 1));
        mt0 = fmaxf(mt0, __shfl_xor_sync(0xffffffffu, mt0, 2));
        mt1 = fmaxf(mt1, __shfl_xor_sync(0xffffffffu, mt1, 1));
        mt1 = fmaxf(mt1, __shfl_xor_sync(0xffffffffu, mt1, 2));

        // ---- online softmax update ----
        float m0n = fmaxf(m0, mt0), m1n = fmaxf(m1, mt1);
        float sf0 = __expf(m0 - m0n), sf1 = __expf(m1 - m1n);
        m0 = m0n; m1 = m1n;
        float rs0 = 0.f, rs1 = 0.f;
#pragma unroll
        for (int nt = 0; nt < 4; nt++) {
            float p0 = __expf(C[nt][0] - m0);
            float p1 = __expf(C[nt][1] - m0);
            float p2 = __expf(C[nt][2] - m1);
            float p3 = __expf(C[nt][3] - m1);
            C[nt][0] = p0; C[nt][1] = p1; C[nt][2] = p2; C[nt][3] = p3;
            rs0 += p0 + p1; rs1 += p2 + p3;
        }
        rs0 += __shfl_xor_sync(0xffffffffu, rs0, 1);
        rs0 += __shfl_xor_sync(0xffffffffu, rs0, 2);
        rs1 += __shfl_xor_sync(0xffffffffu, rs1, 1);
        rs1 += __shfl_xor_sync(0xffffffffu, rs1, 2);
        l0 = l0 * sf0 + rs0;
        l1 = l1 * sf1 + rs1;
#pragma unroll
        for (int n = 0; n < 8; n++) {
            O[n][0] *= sf0; O[n][1] *= sf0;
            O[n][2] *= sf1; O[n][3] *= sf1;
        }
        // ---- AV MMA: exp(S) frags from registers ----
#pragma unroll
        for (int s2 = 0; s2 < 2; s2++) {
            uint4 af = make_uint4(
                pkh2f(C[2 * s2][0], C[2 * s2][1]),
                pkh2f(C[2 * s2][2], C[2 * s2][3]),
                pkh2f(C[2 * s2 + 1][0], C[2 * s2 + 1][1]),
                pkh2f(C[2 * s2 + 1][2], C[2 * s2 + 1][3]));
#pragma unroll
            for (int n = 0; n < 8; n++) {
                uint2 bv = *(const uint2*)&sV[(ch * 2 + s2) * 520 + n * 64 + lam * 2];
                mma_f16(O[n], af, bv);
            }
        }
    }

    // ===================== split-k merge across ch pairs =====================
    __syncthreads();
    if (ch == 1) {
#pragma unroll
        for (int n = 0; n < 8; n++) {
            int hd = n * 8 + la2;
            *(float2*)&mO[gr0 * 68 + hd]       = make_float2(O[n][0], O[n][1]);
            *(float2*)&mO[(gr0 + 8) * 68 + hd] = make_float2(O[n][2], O[n][3]);
        }
        if ((lam & 3) == 0) {
            mml[gr0 * 2 + 0] = m0; mml[gr0 * 2 + 1] = l0;
            mml[(gr0 + 8) * 2 + 0] = m1; mml[(gr0 + 8) * 2 + 1] = l1;
        }
    }
    __syncthreads();
    if (ch == 0) {
        float ma = mml[gr0 * 2 + 0], la = mml[gr0 * 2 + 1];
        float mt = fmaxf(m0, ma);
        float e0 = __expf(m0 - mt), e1 = __expf(ma - mt);
        float inv0 = 1.f / (l0 * e0 + la * e1);
        float mb = mml[(gr0 + 8) * 2 + 0], lb = mml[(gr0 + 8) * 2 + 1];
        float mtb = fmaxf(m1, mb);
        float f0 = __expf(m1 - mtb), f1 = __expf(mb - mtb);
        float inv1 = 1.f / (l1 * f0 + lb * f1);
#pragma unroll
        for (int n = 0; n < 8; n++) {
            int hd = n * 8 + la2;
            if (r0g < NL) {
                float2 oc = *(float2*)&mO[gr0 * 68 + hd];
                float2 st = make_float2((O[n][0] * e0 + oc.x * e1) * inv0,
                                        (O[n][1] * e0 + oc.y * e1) * inv0);
                *(float2*)&ctx[((size_t)b * NL + r0g) * ND + h * 64 + hd] = st;
            }
            if (r1g < NL) {
                float2 oc = *(float2*)&mO[(gr0 + 8) * 68 + hd];
                float2 st = make_float2((O[n][2] * f0 + oc.x * f1) * inv1,
                                        (O[n][3] * f0 + oc.y * f1) * inv1);
                *(float2*)&ctx[((size_t)b * NL + r1g) * ND + h * 64 + hd] = st;
            }
        }
    }
}

// ---------------------------------------------------------------------------
extern "C" void kernel_launch(void* const* d_in, const int* in_sizes, int n_in,
                              void* d_out, int out_size)
{
    const float* x     = (const float*)d_in[0];
    const float* pe    = (const float*)d_in[1];
    const unsigned char* mask = (const unsigned char*)d_in[2];
    const float* qkv_w = (const float*)d_in[3];
    const float* qkv_b = (const float*)d_in[4];
    const float* pos_w = (const float*)d_in[5];
    const float* pos_b = (const float*)d_in[6];
    const float* out_w = (const float*)d_in[7];
    const float* out_b = (const float*)d_in[8];
    const float* cbias = (const float*)d_in[9];
    const float* pbias = (const float*)d_in[10];
    float* out = (float*)d_out;

    float* ctxp = nullptr;
    cudaGetSymbolAddress((void**)&ctxp, g_CTX);

    const int M1 = NB * NL;                        // 8208
    const int GEMM_SMEM = 2 * (2120 + 2052) * 4;   // 33,376 B
    const int ATTN_SMEM = 12416 * 4;               // 49,664 B
    cudaFuncSetAttribute(gemm_fused, cudaFuncAttributeMaxDynamicSharedMemorySize, GEMM_SMEM);
    cudaFuncSetAttribute(gemm_out,   cudaFuncAttributeMaxDynamicSharedMemorySize, GEMM_SMEM);
    cudaFuncSetAttribute(attn_flash, cudaFuncAttributeMaxDynamicSharedMemorySize, ATTN_SMEM);

    dim3 blk(256);
    // fused QKV (1560 CTAs) + POS (1024 CTAs) projections
    gemm_fused<<<2584, blk, GEMM_SMEM>>>(
        x, qkv_w, qkv_b, cbias, pbias, pos_w, pe, pos_b);
    attn_flash<<<dim3(9, NH, NB), blk, ATTN_SMEM>>>(mask, ctxp);
    gemm_out<<<dim3(1024 / 128, (M1 + 127) / 128), blk, GEMM_SMEM>>>(
        nullptr, out_w, M1, 1024, out_b, out);
}

// round 16
// speedup vs baseline: 1.1349x; 1.0377x over previous
#include <cuda_runtime.h>
#include <cuda_fp16.h>
#include <math.h>

#define NB 16
#define NH 16
#define NHD 64
#define ND 1024
#define NL 513
#define NP 1024

#define NX4   2101248   // x      8208*1024 /4
#define NQW4   786432   // qkv_w  3072*1024 /4
#define NPW4   262144   // pos_w  1024*1024 /4
#define NPE4  4194304   // pe     16*16*64*1024 /4
#define NOW4   262144   // out_w  1024*1024 /4

// Scratch (allocation-free rule: __device__ globals). fp16 everywhere.
__device__ __half g_Xh [NX4*4];
__device__ __half g_QWh[NQW4*4];
__device__ __half g_PWh[NPW4*4];
__device__ __half g_PEh[NPE4*4];
__device__ __half g_OWh[NOW4*4];
__device__ __half g_QCh[NB*NH*NL*NHD];   // q + content_bias
__device__ __half g_QPh[NB*NH*NL*NHD];   // q + position_bias
__device__ __half g_Kh [NB*NH*NL*NHD];
__device__ __half g_Vh [NB*NH*NL*NHD];
__device__ __half g_PTh[NB*NH*NP*NHD];
__device__ __half g_CTXh[NB*NL*ND];      // attention output (fp16)

__device__ __forceinline__ void mma_f16(float* d, const uint4& a, const uint2& b) {
    asm volatile(
        "mma.sync.aligned.m16n8k16.row.col.f32.f16.f16.f32 "
        "{%0,%1,%2,%3}, {%4,%5,%6,%7}, {%8,%9}, {%0,%1,%2,%3};"
        : "+f"(d[0]), "+f"(d[1]), "+f"(d[2]), "+f"(d[3])
        : "r"(a.x), "r"(a.y), "r"(a.z), "r"(a.w), "r"(b.x), "r"(b.y));
}

__device__ __forceinline__ unsigned pkh2f(float x, float y) {
    __half2 h = __floats2half2_rn(x, y);
    return *(unsigned*)&h;
}
__device__ __forceinline__ unsigned pkhh(__half x, __half y) {
    __half2 h = __halves2half2(x, y);
    return *(unsigned*)&h;
}

// ---------------------------------------------------------------------------
// One-shot fp32 -> fp16 conversion (streaming, bandwidth-bound).
// Pairing matches pkh2f((v.x,v.y)),( (v.z,v.w)) -> staging values bit-identical.
// ---------------------------------------------------------------------------
__global__ void cvt_all(const float* __restrict__ x, const float* __restrict__ qw,
                        const float* __restrict__ pw, const float* __restrict__ pe,
                        const float* __restrict__ ow)
{
    int tid = blockIdx.x * blockDim.x + threadIdx.x;
    int stride = gridDim.x * blockDim.x;
#define CVT(SRC, DST, N4)                                    \
    for (int i = tid; i < (N4); i += stride) {               \
        float4 v = ((const float4*)(SRC))[i];                \
        uint2 o;                                             \
        o.x = pkh2f(v.x, v.y); o.y = pkh2f(v.z, v.w);        \
        ((uint2*)(DST))[i] = o;                              \
    }
    CVT(x,  g_Xh,  NX4)
    CVT(qw, g_QWh, NQW4)
    CVT(pw, g_PWh, NPW4)
    CVT(pe, g_PEh, NPE4)
    CVT(ow, g_OWh, NOW4)
#undef CVT
}

// ---------------------------------------------------------------------------
// Fused QKV + POS projections in ONE grid. Inputs pre-converted fp16:
// staging loads are uint2, stores are direct (no cvt in the mainloop).
// Same fragment-layout smem mapping as the measured-best config.
// ---------------------------------------------------------------------------
__global__ void __launch_bounds__(256, 2)
gemm_fused(const float* __restrict__ qb, const float* __restrict__ cb,
           const float* __restrict__ pbv, const float* __restrict__ posb)
{
    const int K = 1024;
    extern __shared__ unsigned gsm[];
    unsigned* sA = gsm;            // 2 x 2120
    unsigned* sB = gsm + 2 * 2120; // 2 x 2052

    int bid = blockIdx.x;
    int epi, m0, n0, M;
    const __half *A, *Bw;
    if (bid < 1560) {
        epi = 0; m0 = (bid / 24) * 128; n0 = (bid % 24) * 128;
        A = g_Xh; Bw = g_QWh; M = NB * NL;
    } else {
        int i2 = bid - 1560;
        epi = 1; m0 = (i2 % 8) * 128; n0 = (i2 / 8) * 128;
        A = g_PWh; Bw = g_PEh; M = 1024;
    }

    int t    = threadIdx.x;
    int lane = t & 31, w = t >> 5;
    int warpM = w & 1, warpN = w >> 1;

    int lrow = t >> 3;
    int lkq  = t & 7;
    int kk0  = lkq * 4;
    int sstep = kk0 >> 4;
    int c16  = kk0 & 15;

    unsigned baA[4], baB[4];
#pragma unroll
    for (int u = 0; u < 4; u++) {
        int ml = lrow + u * 32;
        int mt = ml >> 4, mr = ml & 15;
        baA[u] = sstep * 1060 + mt * 132
               + ((mr & 7) * 4 + ((c16 & 7) >> 1)) * 4
               + (c16 >> 3) * 2 + (mr >> 3);
        baB[u] = sstep * 1026 + (ml >> 3) * 64
               + ((ml & 7) * 4 + ((c16 & 7) >> 1)) * 2
               + (c16 >> 3);
    }

    float acc[4][4][4];
#pragma unroll
    for (int i = 0; i < 4; i++)
#pragma unroll
        for (int j = 0; j < 4; j++)
#pragma unroll
            for (int r = 0; r < 4; r++) acc[i][j][r] = 0.f;

    uint2 ra[4], rb[4];
    const uint2 z2 = make_uint2(0u, 0u);

#define GLOADF(KT) {                                                         \
        _Pragma("unroll")                                                    \
        for (int u = 0; u < 4; u++) {                                        \
            int gm = m0 + lrow + u * 32;                                     \
            ra[u] = (gm < M) ? *(const uint2*)(A + (size_t)gm * K + (KT) + kk0) : z2; \
            rb[u] = *(const uint2*)(Bw + (size_t)(n0 + lrow + u * 32) * K + (KT) + kk0); \
        } }

#define SSTOREF(BI) {                                                        \
        _Pragma("unroll")                                                    \
        for (int u = 0; u < 4; u++) {                                        \
            unsigned ba = (BI) * 2120 + baA[u];                              \
            sA[ba + 0] = ra[u].x;                                            \
            sA[ba + 4] = ra[u].y;                                            \
            unsigned bb = (BI) * 2052 + baB[u];                              \
            sB[bb + 0] = rb[u].x;                                            \
            sB[bb + 2] = rb[u].y;                                            \
        } }

    GLOADF(0);
    SSTOREF(0);
    __syncthreads();

    for (int c = 0; c < 32; c++) {
        int cur = c & 1;
        if (c < 31) GLOADF((c + 1) * 32);
#pragma unroll
        for (int s = 0; s < 2; s++) {
            uint4 av[4];
            uint2 bv[4];
#pragma unroll
            for (int i = 0; i < 4; i++)
                av[i] = *(const uint4*)&sA[cur * 2120 + s * 1060 + (warpM * 4 + i) * 132 + lane * 4];
#pragma unroll
            for (int j = 0; j < 4; j++)
                bv[j] = *(const uint2*)&sB[cur * 2052 + s * 1026 + (warpN * 4 + j) * 64 + lane * 2];
#pragma unroll
            for (int i = 0; i < 4; i++)
#pragma unroll
                for (int j = 0; j < 4; j++)
                    mma_f16(acc[i][j], av[i], bv[j]);
        }
        if (c < 31) SSTOREF(1 - cur);
        __syncthreads();
    }
#undef GLOADF
#undef SSTOREF

    int mb = m0 + warpM * 64 + (lane >> 2);
    int nb = n0 + warpN * 32 + (lane & 3) * 2;
#pragma unroll
    for (int i = 0; i < 4; i++) {
#pragma unroll
        for (int rr = 0; rr < 2; rr++) {
            int m = mb + i * 16 + rr * 8;
            if (m >= M) continue;
            if (epi == 0) {
                int b_ = m / NL, l = m - b_ * NL;
#pragma unroll
                for (int j = 0; j < 4; j++) {
                    int n = nb + j * 8;
                    float v0 = acc[i][j][rr * 2 + 0] + qb[n];
                    float v1 = acc[i][j][rr * 2 + 1] + qb[n + 1];
                    int part = n >> 10, c1 = n & 1023;
                    int hh = c1 >> 6, hd = c1 & 63;
                    size_t o = ((((size_t)b_ * NH + hh) * NL + l) << 6) + hd;
                    if (part == 0) {
                        *(unsigned*)&g_QCh[o] = pkh2f(v0 + cb[c1], v1 + cb[c1 + 1]);
                        *(unsigned*)&g_QPh[o] = pkh2f(v0 + pbv[c1], v1 + pbv[c1 + 1]);
                    } else if (part == 1) {
                        *(unsigned*)&g_Kh[o] = pkh2f(v0, v1);
                    } else {
                        *(unsigned*)&g_Vh[o] = pkh2f(v0, v1);
                    }
                }
            } else {
                float bm = posb[m];
#pragma unroll
                for (int j = 0; j < 4; j++) {
                    int n = nb + j * 8;
                    float v0 = acc[i][j][rr * 2 + 0] + bm;
                    float v1 = acc[i][j][rr * 2 + 1] + bm;
                    int bh = n >> 6, hd = n & 63;
                    *(unsigned*)&g_PTh[((((size_t)bh) << 10) + m) * 64 + hd] = pkh2f(v0, v1);
                }
            }
        }
    }
}

// ---------------------------------------------------------------------------
// Output projection: A = fp16 ctx, B = fp16 out_w (both pre-converted).
// ---------------------------------------------------------------------------
__global__ void __launch_bounds__(256, 2)
gemm_out(int M, const float* __restrict__ bias, float* __restrict__ out)
{
    const int K = 1024;
    extern __shared__ unsigned gsm[];
    unsigned* sA = gsm;
    unsigned* sB = gsm + 2 * 2120;
    const __half* A  = g_CTXh;
    const __half* Bw = g_OWh;

    int t    = threadIdx.x;
    int lane = t & 31, w = t >> 5;
    int warpM = w & 1, warpN = w >> 1;
    int m0 = blockIdx.y * 128, n0 = blockIdx.x * 128;

    int lrow = t >> 3;
    int lkq  = t & 7;
    int kk0  = lkq * 4;
    int sstep = kk0 >> 4;
    int c16  = kk0 & 15;

    unsigned baA[4], baB[4];
#pragma unroll
    for (int u = 0; u < 4; u++) {
        int ml = lrow + u * 32;
        int mt = ml >> 4, mr = ml & 15;
        baA[u] = sstep * 1060 + mt * 132
               + ((mr & 7) * 4 + ((c16 & 7) >> 1)) * 4
               + (c16 >> 3) * 2 + (mr >> 3);
        baB[u] = sstep * 1026 + (ml >> 3) * 64
               + ((ml & 7) * 4 + ((c16 & 7) >> 1)) * 2
               + (c16 >> 3);
    }

    float acc[4][4][4];
#pragma unroll
    for (int i = 0; i < 4; i++)
#pragma unroll
        for (int j = 0; j < 4; j++)
#pragma unroll
            for (int r = 0; r < 4; r++) acc[i][j][r] = 0.f;

    uint2 ra[4], rb[4];
    const uint2 z2 = make_uint2(0u, 0u);

#define GLOADO(KT) {                                                         \
        _Pragma("unroll")                                                    \
        for (int u = 0; u < 4; u++) {                                        \
            int gm = m0 + lrow + u * 32;                                     \
            ra[u] = (gm < M) ? *(const uint2*)(A + (size_t)gm * K + (KT) + kk0) : z2; \
            rb[u] = *(const uint2*)(Bw + (size_t)(n0 + lrow + u * 32) * K + (KT) + kk0); \
        } }

#define SSTOREO(BI) {                                                        \
        _Pragma("unroll")                                                    \
        for (int u = 0; u < 4; u++) {                                        \
            unsigned ba = (BI) * 2120 + baA[u];                              \
            sA[ba + 0] = ra[u].x;                                            \
            sA[ba + 4] = ra[u].y;                                            \
            unsigned bb = (BI) * 2052 + baB[u];                              \
            sB[bb + 0] = rb[u].x;                                            \
            sB[bb + 2] = rb[u].y;                                            \
        } }

    GLOADO(0);
    SSTOREO(0);
    __syncthreads();

    for (int c = 0; c < 32; c++) {
        int cur = c & 1;
        if (c < 31) GLOADO((c + 1) * 32);
#pragma unroll
        for (int s = 0; s < 2; s++) {
            uint4 av[4];
            uint2 bv[4];
#pragma unroll
            for (int i = 0; i < 4; i++)
                av[i] = *(const uint4*)&sA[cur * 2120 + s * 1060 + (warpM * 4 + i) * 132 + lane * 4];
#pragma unroll
            for (int j = 0; j < 4; j++)
                bv[j] = *(const uint2*)&sB[cur * 2052 + s * 1026 + (warpN * 4 + j) * 64 + lane * 2];
#pragma unroll
            for (int i = 0; i < 4; i++)
#pragma unroll
                for (int j = 0; j < 4; j++)
                    mma_f16(acc[i][j], av[i], bv[j]);
        }
        if (c < 31) SSTOREO(1 - cur);
        __syncthreads();
    }
#undef GLOADO
#undef SSTOREO

    int mb = m0 + warpM * 64 + (lane >> 2);
    int nb = n0 + warpN * 32 + (lane & 3) * 2;
#pragma unroll
    for (int i = 0; i < 4; i++) {
#pragma unroll
        for (int rr = 0; rr < 2; rr++) {
            int m = mb + i * 16 + rr * 8;
            if (m >= M) continue;
#pragma unroll
            for (int j = 0; j < 4; j++) {
                int n = nb + j * 8;
                float2 st;
                st.x = acc[i][j][rr * 2 + 0] + bias[n];
                st.y = acc[i][j][rr * 2 + 1] + bias[n + 1];
                *(float2*)(out + (size_t)m * ND + n) = st;
            }
        }
    }
}

// ---------------------------------------------------------------------------
// Flash-style fused attention (R15 passing config; ctx stored fp16).
// CTA = 64 q x (b,h); 8 warps: rg=w&3 rows, ch=w>>2 key-chunk.
// Dynamic smem 49,664 B -> 2 CTAs/SM.
// ---------------------------------------------------------------------------
__global__ void __launch_bounds__(256, 2)
attn_flash(const unsigned char* __restrict__ mask, __half* __restrict__ ctx)
{
    extern __shared__ unsigned smu[];
    unsigned* sK = smu;                 // 2080 uints (4 x 520)
    unsigned* sV = smu + 2080;          // 2080 uints
    unsigned* sP = smu + 4160;          // 4096 uints (4 x 1024)
    __half*   sG = (__half*)(smu + 8256); // 64 x 130 halves (4160 uints)
    float* mO  = (float*)smu;           // merge overlay [64][68]
    float* mml = (float*)smu + 64 * 68; // [64][2]

    const float NEG = -3.4028235e38f;
    int t = threadIdx.x, lam = t & 31, w = t >> 5;
    int rg = w & 3, ch = w >> 2;
    int it = blockIdx.x, h = blockIdx.y, b = blockIdx.z;
    int i0 = it * 64;
    size_t bh = (size_t)b * NH + h;
    const __half* QCg = g_QCh + bh * NL * NHD;
    const __half* QPg = g_QPh + bh * NL * NHD;
    const __half* Kg  = g_Kh  + bh * NL * NHD;
    const __half* Vg  = g_Vh  + bh * NL * NHD;
    const __half* Pg  = g_PTh + bh * NP * NHD;

    int gr0 = rg * 16 + (lam >> 2);
    int r0g = i0 + gr0, r1g = r0g + 8;
    int gt0 = 6 - 2 * rg;
    int vkey = t >> 4;
    int vhd4 = (t & 15) * 4;
    int la2  = (lam & 3) * 2;

    const unsigned char* mrow0 = mask + ((size_t)b * NL + (r0g < NL ? r0g : NL - 1)) * NL;
    const unsigned char* mrow1 = mask + ((size_t)b * NL + (r1g < NL ? r1g : NL - 1)) * NL;

    // Q frags, prescaled by 1/8 (exact power of 2)
    __half2 hsc = __float2half2_rn(0.125f);
    uint4 qcf[4], qpf[4];
#pragma unroll
    for (int s = 0; s < 4; s++) {
        int c0 = s * 16 + la2;
        __half2 v;
        unsigned r[8] = {0,0,0,0,0,0,0,0};
        if (r0g < NL) {
            v = __hmul2(*(const __half2*)(QCg + r0g * 64 + c0), hsc);     r[0] = *(unsigned*)&v;
            v = __hmul2(*(const __half2*)(QCg + r0g * 64 + c0 + 8), hsc); r[2] = *(unsigned*)&v;
            v = __hmul2(*(const __half2*)(QPg + r0g * 64 + c0), hsc);     r[4] = *(unsigned*)&v;
            v = __hmul2(*(const __half2*)(QPg + r0g * 64 + c0 + 8), hsc); r[6] = *(unsigned*)&v;
        }
        if (r1g < NL) {
            v = __hmul2(*(const __half2*)(QCg + r1g * 64 + c0), hsc);     r[1] = *(unsigned*)&v;
            v = __hmul2(*(const __half2*)(QCg + r1g * 64 + c0 + 8), hsc); r[3] = *(unsigned*)&v;
            v = __hmul2(*(const __half2*)(QPg + r1g * 64 + c0), hsc);     r[5] = *(unsigned*)&v;
            v = __hmul2(*(const __half2*)(QPg + r1g * 64 + c0 + 8), hsc); r[7] = *(unsigned*)&v;
        }
        qcf[s] = make_uint4(r[0], r[1], r[2], r[3]);
        qpf[s] = make_uint4(r[4], r[5], r[6], r[7]);
    }

    float O[8][4];
#pragma unroll
    for (int n = 0; n < 8; n++)
#pragma unroll
        for (int r = 0; r < 4; r++) O[n][r] = 0.f;
    float m0 = NEG, m1 = NEG, l0 = 0.f, l1 = 0.f;

    for (int jt = 0; jt < 9; jt++) {
        int j0 = jt * 64;
        int xorv = (jt & 1) << 3;
        __syncthreads();   // staging writes vs all prev-jt reads (K,V,P,G)

        // ---- stage K tile (B-frags, k=hd, n=key) ----
        {
            int step = vhd4 >> 4, k16 = vhd4 & 15;
            unsigned boff = step * 520 + ((k16 & 7) >> 1) * 2 + (k16 >> 3);
#pragma unroll
            for (int u = 0; u < 4; u++) {
                int key = vkey + u * 16;
                int gk = j0 + key;
                uint2 kv = make_uint2(0u, 0u);
                if (gk < NL) kv = *(const uint2*)(Kg + (size_t)gk * 64 + vhd4);
                unsigned base = boff + (key >> 3) * 64 + (key & 7) * 8;
                sK[base]     = kv.x;
                sK[base + 2] = kv.y;
            }
        }
        // ---- stage V tile (B-frags, k=key, n=hd); rotated store order ----
#pragma unroll
        for (int u = 0; u < 2; u++) {
            int k0 = 2 * vkey + 32 * u;
            int gk = j0 + k0;
            uint2 a = (gk < NL)     ? *(const uint2*)(Vg + (size_t)gk * 64 + vhd4)       : make_uint2(0u, 0u);
            uint2 bq = (gk + 1 < NL) ? *(const uint2*)(Vg + (size_t)(gk + 1) * 64 + vhd4) : make_uint2(0u, 0u);
            __half2 a01 = *(__half2*)&a.x,  a23 = *(__half2*)&a.y;
            __half2 b01 = *(__half2*)&bq.x, b23 = *(__half2*)&bq.y;
            unsigned o0 = pkhh(a01.x, b01.x);
            unsigned o1 = pkhh(a01.y, b01.y);
            unsigned o2 = pkhh(a23.x, b23.x);
            unsigned o3 = pkhh(a23.y, b23.y);
            int step = k0 >> 4, kk = k0 & 15;
            unsigned koff = step * 520 + ((kk & 7) >> 1) * 2 + (kk >> 3)
                          + (vhd4 >> 3) * 64 + (vhd4 & 4) * 8;
            int rot = lam & 3;
#pragma unroll
            for (int e4 = 0; e4 < 4; e4++) {
                int e = (e4 + rot) & 3;
                unsigned v = (e == 0) ? o0 : (e == 1) ? o1 : (e == 2) ? o2 : o3;
                sV[koff + e * 8] = v;
            }
        }
        // ---- stage P band (circular: full 128 rows at jt=0, 64 new after) ----
        int pbase = j0 - i0 + 449;
        if (jt == 0) {
#pragma unroll
            for (int u = 0; u < 8; u++) {
                int idx = u * 256 + t;
                int c = idx >> 4, d4 = (idx & 15) * 4;
                int p = pbase + c;
                uint2 pv = make_uint2(0u, 0u);
                if ((unsigned)p < (unsigned)NP)
                    pv = *(const uint2*)(Pg + (size_t)p * 64 + d4);
                int step = d4 >> 4, k16 = d4 & 15;
                unsigned a0 = step * 1024 + (c >> 3) * 64 + ((c & 7) * 4 + ((k16 & 7) >> 1)) * 2 + (k16 >> 3);
                sP[a0]     = pv.x;
                sP[a0 + 2] = pv.y;
            }
        } else {
#pragma unroll
            for (int u = 0; u < 4; u++) {
                int idx = u * 256 + t;
                int c = 64 + (idx >> 4), d4 = (idx & 15) * 4;
                int p = pbase + c;
                uint2 pv = make_uint2(0u, 0u);
                if ((unsigned)p < (unsigned)NP)
                    pv = *(const uint2*)(Pg + (size_t)p * 64 + d4);
                int step = d4 >> 4, k16 = d4 & 15;
                unsigned a0 = step * 1024 + ((c >> 3) ^ xorv) * 64 + ((c & 7) * 4 + ((k16 & 7) >> 1)) * 2 + (k16 >> 3);
                sP[a0]     = pv.x;
                sP[a0 + 2] = pv.y;
            }
        }
        __syncthreads();

        // ---- content MMA ----
        float C[4][4];
#pragma unroll
        for (int nt = 0; nt < 4; nt++)
#pragma unroll
            for (int r = 0; r < 4; r++) C[nt][r] = 0.f;
#pragma unroll
        for (int s = 0; s < 4; s++) {
#pragma unroll
            for (int nt = 0; nt < 4; nt++) {
                uint2 bv = *(const uint2*)&sK[s * 520 + (ch * 4 + nt) * 64 + lam * 2];
                mma_f16(C[nt], qcf[s], bv);
            }
        }
        // ---- G MMA (band-pruned) + store ----
        {
            float G[5][4];
#pragma unroll
            for (int nt = 0; nt < 5; nt++)
#pragma unroll
                for (int r = 0; r < 4; r++) G[nt][r] = 0.f;
#pragma unroll
            for (int s = 0; s < 4; s++) {
#pragma unroll
                for (int nt = 0; nt < 5; nt++) {
                    int tg = (gt0 + ch * 5 + nt) ^ xorv;
                    uint2 bv = *(const uint2*)&sP[s * 1024 + tg * 64 + lam * 2];
                    mma_f16(G[nt], qpf[s], bv);
                }
            }
#pragma unroll
            for (int nt = 0; nt < 5; nt++) {
                int c0 = (gt0 + ch * 5 + nt) * 8 + la2;
                *(__half2*)&sG[gr0 * 130 + c0]       = __floats2half2_rn(G[nt][0], G[nt][1]);
                *(__half2*)&sG[(gr0 + 8) * 130 + c0] = __floats2half2_rn(G[nt][2], G[nt][3]);
            }
        }
        __syncthreads();   // G visible to both ch warps

        // ---- gather + mask -> masked scaled scores in C ----
        float mt0 = NEG, mt1 = NEG;
#pragma unroll
        for (int nt = 0; nt < 4; nt++) {
            int jjb = ch * 32 + nt * 8 + la2;
            int jc = j0 + jjb;
            float s0 = C[nt][0] + __half2float(sG[gr0 * 130 + (jjb - gr0 + 63)]);
            float s1 = C[nt][1] + __half2float(sG[gr0 * 130 + (jjb + 1 - gr0 + 63)]);
            float s2 = C[nt][2] + __half2float(sG[(gr0 + 8) * 130 + (jjb - gr0 - 8 + 63)]);
            float s3 = C[nt][3] + __half2float(sG[(gr0 + 8) * 130 + (jjb + 1 - gr0 - 8 + 63)]);
            s0 = (jc < NL && !mrow0[jc])         ? s0 : NEG;
            s1 = (jc + 1 < NL && !mrow0[jc + 1]) ? s1 : NEG;
            s2 = (jc < NL && !mrow1[jc])         ? s2 : NEG;
            s3 = (jc + 1 < NL && !mrow1[jc + 1]) ? s3 : NEG;
            C[nt][0] = s0; C[nt][1] = s1; C[nt][2] = s2; C[nt][3] = s3;
            mt0 = fmaxf(mt0, fmaxf(s0, s1));
            mt1 = fmaxf(mt1, fmaxf(s2, s3));
        }
        mt0 = fmaxf(mt0, __shfl_xor_sync(0xffffffffu, mt0, 1));
        mt0 = fmaxf(mt0, __shfl_xor_sync(0xffffffffu, mt0, 2));
        mt1 = fmaxf(mt1, __shfl_xor_sync(0xffffffffu, mt1, 1));
        mt1 = fmaxf(mt1, __shfl_xor_sync(0xffffffffu, mt1, 2));

        // ---- online softmax update ----
        float m0n = fmaxf(m0, mt0), m1n = fmaxf(m1, mt1);
        float sf0 = __expf(m0 - m0n), sf1 = __expf(m1 - m1n);
        m0 = m0n; m1 = m1n;
        float rs0 = 0.f, rs1 = 0.f;
#pragma unroll
        for (int nt = 0; nt < 4; nt++) {
            float p0 = __expf(C[nt][0] - m0);
            float p1 = __expf(C[nt][1] - m0);
            float p2 = __expf(C[nt][2] - m1);
            float p3 = __expf(C[nt][3] - m1);
            C[nt][0] = p0; C[nt][1] = p1; C[nt][2] = p2; C[nt][3] = p3;
            rs0 += p0 + p1; rs1 += p2 + p3;
        }
        rs0 += __shfl_xor_sync(0xffffffffu, rs0, 1);
        rs0 += __shfl_xor_sync(0xffffffffu, rs0, 2);
        rs1 += __shfl_xor_sync(0xffffffffu, rs1, 1);
        rs1 += __shfl_xor_sync(0xffffffffu, rs1, 2);
        l0 = l0 * sf0 + rs0;
        l1 = l1 * sf1 + rs1;
#pragma unroll
        for (int n = 0; n < 8; n++) {
            O[n][0] *= sf0; O[n][1] *= sf0;
            O[n][2] *= sf1; O[n][3] *= sf1;
        }
        // ---- AV MMA: exp(S) frags from registers ----
#pragma unroll
        for (int s2 = 0; s2 < 2; s2++) {
            uint4 af = make_uint4(
                pkh2f(C[2 * s2][0], C[2 * s2][1]),
                pkh2f(C[2 * s2][2], C[2 * s2][3]),
                pkh2f(C[2 * s2 + 1][0], C[2 * s2 + 1][1]),
                pkh2f(C[2 * s2 + 1][2], C[2 * s2 + 1][3]));
#pragma unroll
            for (int n = 0; n < 8; n++) {
                uint2 bv = *(const uint2*)&sV[(ch * 2 + s2) * 520 + n * 64 + lam * 2];
                mma_f16(O[n], af, bv);
            }
        }
    }

    // ===================== split-k merge across ch pairs =====================
    __syncthreads();
    if (ch == 1) {
#pragma unroll
        for (int n = 0; n < 8; n++) {
            int hd = n * 8 + la2;
            *(float2*)&mO[gr0 * 68 + hd]       = make_float2(O[n][0], O[n][1]);
            *(float2*)&mO[(gr0 + 8) * 68 + hd] = make_float2(O[n][2], O[n][3]);
        }
        if ((lam & 3) == 0) {
            mml[gr0 * 2 + 0] = m0; mml[gr0 * 2 + 1] = l0;
            mml[(gr0 + 8) * 2 + 0] = m1; mml[(gr0 + 8) * 2 + 1] = l1;
        }
    }
    __syncthreads();
    if (ch == 0) {
        float ma = mml[gr0 * 2 + 0], la = mml[gr0 * 2 + 1];
        float mt = fmaxf(m0, ma);
        float e0 = __expf(m0 - mt), e1 = __expf(ma - mt);
        float inv0 = 1.f / (l0 * e0 + la * e1);
        float mb = mml[(gr0 + 8) * 2 + 0], lb = mml[(gr0 + 8) * 2 + 1];
        float mtb = fmaxf(m1, mb);
        float f0 = __expf(m1 - mtb), f1 = __expf(mb - mtb);
        float inv1 = 1.f / (l1 * f0 + lb * f1);
#pragma unroll
        for (int n = 0; n < 8; n++) {
            int hd = n * 8 + la2;
            if (r0g < NL) {
                float2 oc = *(float2*)&mO[gr0 * 68 + hd];
                *(unsigned*)&ctx[((size_t)b * NL + r0g) * ND + h * 64 + hd] =
                    pkh2f((O[n][0] * e0 + oc.x * e1) * inv0,
                          (O[n][1] * e0 + oc.y * e1) * inv0);
            }
            if (r1g < NL) {
                float2 oc = *(float2*)&mO[(gr0 + 8) * 68 + hd];
                *(unsigned*)&ctx[((size_t)b * NL + r1g) * ND + h * 64 + hd] =
                    pkh2f((O[n][2] * f0 + oc.x * f1) * inv1,
                          (O[n][3] * f0 + oc.y * f1) * inv1);
            }
        }
    }
}

// ---------------------------------------------------------------------------
extern "C" void kernel_launch(void* const* d_in, const int* in_sizes, int n_in,
                              void* d_out, int out_size)
{
    const float* x     = (const float*)d_in[0];
    const float* pe    = (const float*)d_in[1];
    const unsigned char* mask = (const unsigned char*)d_in[2];
    const float* qkv_w = (const float*)d_in[3];
    const float* qkv_b = (const float*)d_in[4];
    const float* pos_w = (const float*)d_in[5];
    const float* pos_b = (const float*)d_in[6];
    const float* out_w = (const float*)d_in[7];
    const float* out_b = (const float*)d_in[8];
    const float* cbias = (const float*)d_in[9];
    const float* pbias = (const float*)d_in[10];
    float* out = (float*)d_out;

    __half* ctxh = nullptr;
    cudaGetSymbolAddress((void**)&ctxh, g_CTXh);

    const int M1 = NB * NL;                        // 8208
    const int GEMM_SMEM = 2 * (2120 + 2052) * 4;   // 33,376 B
    const int ATTN_SMEM = 12416 * 4;               // 49,664 B
    cudaFuncSetAttribute(gemm_fused, cudaFuncAttributeMaxDynamicSharedMemorySize, GEMM_SMEM);
    cudaFuncSetAttribute(gemm_out,   cudaFuncAttributeMaxDynamicSharedMemorySize, GEMM_SMEM);
    cudaFuncSetAttribute(attn_flash, cudaFuncAttributeMaxDynamicSharedMemorySize, ATTN_SMEM);

    dim3 blk(256);
    cvt_all<<<1184, 256>>>(x, qkv_w, pos_w, pe, out_w);
    gemm_fused<<<2584, blk, GEMM_SMEM>>>(qkv_b, cbias, pbias, pos_b);
    attn_flash<<<dim3(9, NH, NB), blk, ATTN_SMEM>>>(mask, ctxh);
    gemm_out<<<dim3(1024 / 128, (M1 + 127) / 128), blk, GEMM_SMEM>>>(M1, out_b, out);
}